// round 8
// baseline (speedup 1.0000x reference)
#include <cuda_runtime.h>
#include <math_constants.h>
#include <stdint.h>

#define HW 3600
#define WDIM 60
#define CCH 128
#define NBATCH 4
#define KTOP 100
#define CAP 65536
#define NBX 29
#define BK 16
#define SPAD 136
#define LCPARTS 15
#define RLCAP 4096
#define MARGIN 0.008f

__device__ float g_sm[(size_t)NBATCH * HW * HW];
__device__ float g_rp[NBATCH * NBX * HW];
__device__ float g_cp[NBATCH * NBX * HW];
__device__ float g_vp[NBATCH * NBX * HW];
__device__ float g_LR[NBATCH * HW];
__device__ float g_LC[NBATCH * HW];
__device__ float g_vmax[NBATCH * HW];
__device__ float g_lcmin_part[NBATCH * LCPARTS];
__device__ float g_lcmax_part[NBATCH * LCPARTS];
__device__ float g_thrv[NBATCH];
__device__ float g_lcmin[NBATCH];
__device__ int   g_cnt[NBATCH];
__device__ float g_cv[NBATCH * CAP];
__device__ int   g_ci[NBATCH * CAP];
__device__ int   g_topi[NBATCH * KTOP];
__device__ float g_E[8 * CCH];
__device__ float g_WX[CCH];
__device__ float g_WY[CCH];
__device__ int   g_rflag[NBATCH * HW];
__device__ int   g_cflag[NBATCH * HW];
__device__ int   g_rlist[NBATCH * RLCAP];
__device__ int   g_clist[NBATCH * RLCAP];
__device__ int   g_rcnt[NBATCH];
__device__ int   g_ccnt[NBATCH];
__device__ float g_LRex[NBATCH * HW];
__device__ float g_LCex[NBATCH * HW];

__device__ __forceinline__ void cp16(float* dst_smem, const float* src, bool ok) {
    unsigned d = (unsigned)__cvta_generic_to_shared(dst_smem);
    int sz = ok ? 16 : 0;
    asm volatile("cp.async.ca.shared.global [%0], [%1], 16, %2;\n" :: "r"(d), "l"(src), "r"(sz));
}
__device__ __forceinline__ void cp_commit() { asm volatile("cp.async.commit_group;\n"); }
__device__ __forceinline__ void cp_wait0()  { asm volatile("cp.async.wait_group 0;\n"); }

__device__ __forceinline__ void mma_tf32(float c[4], const unsigned a[4], const unsigned b[2]) {
    asm volatile(
        "mma.sync.aligned.m16n8k8.row.col.f32.tf32.tf32.f32 "
        "{%0,%1,%2,%3}, {%4,%5,%6,%7}, {%8,%9}, {%0,%1,%2,%3};"
        : "+f"(c[0]), "+f"(c[1]), "+f"(c[2]), "+f"(c[3])
        : "r"(a[0]), "r"(a[1]), "r"(a[2]), "r"(a[3]), "r"(b[0]), "r"(b[1]));
}
__device__ __forceinline__ unsigned to_tf32(float f) {
    unsigned r;
    asm("cvt.rna.tf32.f32 %0, %1;" : "=r"(r) : "f"(f));
    return r;
}
__device__ __forceinline__ unsigned mono_bits(float f) {
    unsigned b = __float_as_uint(f);
    return (b & 0x80000000u) ? ~b : (b | 0x80000000u);
}
__device__ __forceinline__ unsigned long long pack_key(float v, int idx) {
    return ((unsigned long long)mono_bits(v) << 32) |
           (unsigned long long)(0xFFFFFFFFu - (unsigned)idx);
}

// ---------------- approx GEMM (tf32 x1, rna) + fused exp-stats ----------------
__global__ __launch_bounds__(512, 1) void gemm_kernel(const float* __restrict__ x) {
    __shared__ float As[2][BK][SPAD];
    __shared__ float Bs[2][BK][SPAD];
    __shared__ float s_rs[4][128];
    __shared__ float s_rm[4][128];
    __shared__ float s_cs[4][128];

    const int n  = blockIdx.z;
    const int l0 = blockIdx.y * 128;
    const int s0 = blockIdx.x * 128;
    const float* A = x + (size_t)n * CCH * HW;
    const float* B = x + (size_t)(n + NBATCH) * CCH * HW;
    const int tid = threadIdx.x;
    const int lane = tid & 31;
    const int wid = tid >> 5;
    const int g = lane >> 2, tig = lane & 3;
    const int wm = wid & 3, wn = wid >> 2;
    const int rb = wm * 32, cb = wn * 32;

    float acc[2][4][4];
#pragma unroll
    for (int mi = 0; mi < 2; mi++)
#pragma unroll
        for (int ni = 0; ni < 4; ni++)
#pragma unroll
            for (int q = 0; q < 4; q++) acc[mi][ni][q] = 0.0f;

    {
        const int d = tid >> 5;
        const int c4 = lane << 2;
        int colA = l0 + c4; bool okA = colA < HW;
        cp16(&As[0][d][c4], A + (size_t)d * HW + (okA ? colA : 0), okA);
        int colB = s0 + c4; bool okB = colB < HW;
        cp16(&Bs[0][d][c4], B + (size_t)d * HW + (okB ? colB : 0), okB);
    }
    cp_commit();

    for (int c = 0; c < CCH / BK; c++) {
        cp_wait0();
        __syncthreads();
        if (c < CCH / BK - 1) {
            const int kc = c + 1, st = (c + 1) & 1;
            const int d = tid >> 5;
            const int c4 = lane << 2;
            int colA = l0 + c4; bool okA = colA < HW;
            cp16(&As[st][d][c4], A + (size_t)(kc * BK + d) * HW + (okA ? colA : 0), okA);
            int colB = s0 + c4; bool okB = colB < HW;
            cp16(&Bs[st][d][c4], B + (size_t)(kc * BK + d) * HW + (okB ? colB : 0), okB);
            cp_commit();
        }
        const int st = c & 1;
#pragma unroll
        for (int ks = 0; ks < BK; ks += 8) {
            const int k0 = ks + tig;
            unsigned ah[2][4], bh[4][2];
#pragma unroll
            for (int mi = 0; mi < 2; mi++) {
                const int m = rb + mi * 16 + g;
                ah[mi][0] = to_tf32(As[st][k0][m]);
                ah[mi][1] = to_tf32(As[st][k0][m + 8]);
                ah[mi][2] = to_tf32(As[st][k0 + 4][m]);
                ah[mi][3] = to_tf32(As[st][k0 + 4][m + 8]);
            }
#pragma unroll
            for (int ni = 0; ni < 4; ni++) {
                const int nn = cb + ni * 8 + g;
                bh[ni][0] = to_tf32(Bs[st][k0][nn]);
                bh[ni][1] = to_tf32(Bs[st][k0 + 4][nn]);
            }
#pragma unroll
            for (int mi = 0; mi < 2; mi++)
#pragma unroll
                for (int ni = 0; ni < 4; ni++)
                    mma_tf32(acc[mi][ni], ah[mi], bh[ni]);
        }
    }

    const float inv = 1.0f / 12.8f;
    float rsum[2][2], rmax[2][2], csum[4][2];
#pragma unroll
    for (int i = 0; i < 2; i++)
#pragma unroll
        for (int r = 0; r < 2; r++) { rsum[i][r] = 0.0f; rmax[i][r] = -CUDART_INF_F; }
#pragma unroll
    for (int i = 0; i < 4; i++) { csum[i][0] = 0.0f; csum[i][1] = 0.0f; }

#pragma unroll
    for (int mi = 0; mi < 2; mi++) {
        const int row0 = l0 + rb + mi * 16 + g;
        const int row1 = row0 + 8;
        const bool rv0 = row0 < HW, rv1 = row1 < HW;
        float* orow0 = g_sm + ((size_t)(n * HW + row0)) * HW;
        float* orow1 = g_sm + ((size_t)(n * HW + row1)) * HW;
#pragma unroll
        for (int ni = 0; ni < 4; ni++) {
            const int sc0 = s0 + cb + ni * 8 + tig * 2;
            const bool cv0 = sc0 < HW, cv1 = (sc0 + 1) < HW;
            float v0 = acc[mi][ni][0] * inv;
            float v1 = acc[mi][ni][1] * inv;
            float v2 = acc[mi][ni][2] * inv;
            float v3 = acc[mi][ni][3] * inv;
            if (rv0 && cv0) *reinterpret_cast<float2*>(orow0 + sc0) = make_float2(v0, v1);
            if (rv1 && cv0) *reinterpret_cast<float2*>(orow1 + sc0) = make_float2(v2, v3);
            float e0 = cv0 ? __expf(v0) : 0.0f;
            float e1 = cv1 ? __expf(v1) : 0.0f;
            float e2 = cv0 ? __expf(v2) : 0.0f;
            float e3 = cv1 ? __expf(v3) : 0.0f;
            rsum[mi][0] += e0 + e1;
            rsum[mi][1] += e2 + e3;
            rmax[mi][0] = fmaxf(rmax[mi][0], fmaxf(cv0 ? v0 : -CUDART_INF_F, cv1 ? v1 : -CUDART_INF_F));
            rmax[mi][1] = fmaxf(rmax[mi][1], fmaxf(cv0 ? v2 : -CUDART_INF_F, cv1 ? v3 : -CUDART_INF_F));
            csum[ni][0] += (rv0 ? e0 : 0.0f) + (rv1 ? e2 : 0.0f);
            csum[ni][1] += (rv0 ? e1 : 0.0f) + (rv1 ? e3 : 0.0f);
        }
    }

#pragma unroll
    for (int m = 1; m < 4; m <<= 1) {
#pragma unroll
        for (int mi = 0; mi < 2; mi++)
#pragma unroll
            for (int r = 0; r < 2; r++) {
                rsum[mi][r] += __shfl_xor_sync(0xffffffffu, rsum[mi][r], m);
                rmax[mi][r] = fmaxf(rmax[mi][r], __shfl_xor_sync(0xffffffffu, rmax[mi][r], m));
            }
    }
    if (tig == 0) {
#pragma unroll
        for (int mi = 0; mi < 2; mi++) {
            const int rr = rb + mi * 16 + g;
            s_rs[wn][rr] = rsum[mi][0];
            s_rs[wn][rr + 8] = rsum[mi][1];
            s_rm[wn][rr] = rmax[mi][0];
            s_rm[wn][rr + 8] = rmax[mi][1];
        }
    }
#pragma unroll
    for (int m = 4; m < 32; m <<= 1) {
#pragma unroll
        for (int ni = 0; ni < 4; ni++)
#pragma unroll
            for (int q = 0; q < 2; q++)
                csum[ni][q] += __shfl_xor_sync(0xffffffffu, csum[ni][q], m);
    }
    if (g == 0) {
#pragma unroll
        for (int ni = 0; ni < 4; ni++) {
            s_cs[wm][cb + ni * 8 + tig * 2]     = csum[ni][0];
            s_cs[wm][cb + ni * 8 + tig * 2 + 1] = csum[ni][1];
        }
    }
    __syncthreads();
    if (tid < 128) {
        float rs = 0.0f, rm = -CUDART_INF_F;
#pragma unroll
        for (int w = 0; w < 4; w++) { rs += s_rs[w][tid]; rm = fmaxf(rm, s_rm[w][tid]); }
        if (l0 + tid < HW) {
            g_rp[(n * NBX + blockIdx.x) * HW + l0 + tid] = rs;
            g_vp[(n * NBX + blockIdx.x) * HW + l0 + tid] = rm;
        }
        float cs = 0.0f;
#pragma unroll
        for (int w = 0; w < 4; w++) cs += s_cs[w][tid];
        if (s0 + tid < HW)
            g_cp[(n * NBX + blockIdx.y) * HW + s0 + tid] = cs;
    }
}

// ---------------- merge LR,vmax / LC ----------------
__global__ __launch_bounds__(256) void rowfin_kernel() {
    const int n = blockIdx.y;
    const int l = blockIdx.x * 256 + threadIdx.x;
    if (l >= HW) return;
    float s = 0.0f, m = -CUDART_INF_F;
#pragma unroll
    for (int b = 0; b < NBX; b++) {
        s += g_rp[(n * NBX + b) * HW + l];
        m = fmaxf(m, g_vp[(n * NBX + b) * HW + l]);
    }
    g_LR[n * HW + l] = logf(s);
    g_vmax[n * HW + l] = m;
}

__global__ __launch_bounds__(256) void colfin_kernel() {
    const int n = blockIdx.y;
    const int s = blockIdx.x * 256 + threadIdx.x;
    __shared__ float mn[256], mx[256];
    float lo = CUDART_INF_F, hi = -CUDART_INF_F;
    if (s < HW) {
        float acc = 0.0f;
#pragma unroll
        for (int b = 0; b < NBX; b++) acc += g_cp[(n * NBX + b) * HW + s];
        float v = logf(acc);
        g_LC[n * HW + s] = v;
        lo = v; hi = v;
    }
    const int tid = threadIdx.x;
    mn[tid] = lo; mx[tid] = hi;
    __syncthreads();
    for (int o = 128; o > 0; o >>= 1) {
        if (tid < o) {
            mn[tid] = fminf(mn[tid], mn[tid + o]);
            mx[tid] = fmaxf(mx[tid], mx[tid + o]);
        }
        __syncthreads();
    }
    if (tid == 0) {
        g_lcmin_part[n * LCPARTS + blockIdx.x] = mn[0];
        g_lcmax_part[n * LCPARTS + blockIdx.x] = mx[0];
    }
}

// ---------------- threshold (margin for exact rescore) + scratch reset ----------------
__global__ __launch_bounds__(256) void bound_kernel() {
    const int n = blockIdx.x;
    const int tid = threadIdx.x;
    __shared__ float s_lcmax;
    __shared__ float red1[256], red2[256];
    __shared__ int hist[2048];
    __shared__ unsigned ssum[256];
    __shared__ float s_lmn, s_lmx;

    for (int i = tid; i < HW; i += 256) { g_rflag[n * HW + i] = 0; g_cflag[n * HW + i] = 0; }
    if (tid == 0) {
        float mn = CUDART_INF_F, mx = -CUDART_INF_F;
        for (int i = 0; i < LCPARTS; i++) {
            mn = fminf(mn, g_lcmin_part[n * LCPARTS + i]);
            mx = fmaxf(mx, g_lcmax_part[n * LCPARTS + i]);
        }
        g_lcmin[n] = mn;
        s_lcmax = mx;
        g_cnt[n] = 0; g_rcnt[n] = 0; g_ccnt[n] = 0;
    }
    __syncthreads();
    const float lcmax = s_lcmax;

    float lmn = CUDART_INF_F, lmx = -CUDART_INF_F;
    for (int l = tid; l < HW; l += 256) {
        float L = fmaf(2.0f, g_vmax[n * HW + l], -g_LR[n * HW + l]) - lcmax;
        lmn = fminf(lmn, L); lmx = fmaxf(lmx, L);
    }
    red1[tid] = lmn; red2[tid] = lmx;
    __syncthreads();
    for (int o = 128; o > 0; o >>= 1) {
        if (tid < o) {
            red1[tid] = fminf(red1[tid], red1[tid + o]);
            red2[tid] = fmaxf(red2[tid], red2[tid + o]);
        }
        __syncthreads();
    }
    if (tid == 0) { s_lmn = red1[0]; s_lmx = red2[0]; }
    __syncthreads();
    const float Lmn = s_lmn;
    const float binw = (s_lmx - Lmn) * (1.0f / 2048.0f);
    if (binw < 1e-30f) {
        if (tid == 0) g_thrv[n] = Lmn - MARGIN;
        return;
    }
    for (int i = tid; i < 2048; i += 256) hist[i] = 0;
    __syncthreads();
    for (int l = tid; l < HW; l += 256) {
        float L = fmaf(2.0f, g_vmax[n * HW + l], -g_LR[n * HW + l]) - lcmax;
        int b = (int)((L - Lmn) / binw);
        b = max(0, min(2047, b));
        atomicAdd(&hist[b], 1);
    }
    __syncthreads();
    unsigned csum = 0;
#pragma unroll
    for (int i = 0; i < 8; i++) csum += (unsigned)hist[tid * 8 + i];
    ssum[tid] = csum;
    __syncthreads();
    for (int off = 1; off < 256; off <<= 1) {
        unsigned v = (tid + off < 256) ? ssum[tid + off] : 0u;
        __syncthreads();
        ssum[tid] += v;
        __syncthreads();
    }
    unsigned mine = ssum[tid];
    unsigned nxt = (tid < 255) ? ssum[tid + 1] : 0u;
    if (mine >= KTOP && nxt < KTOP) {
        unsigned cum = nxt;
        int b = tid * 8 + 7;
        for (; b > tid * 8; b--) {
            cum += (unsigned)hist[b];
            if (cum >= KTOP) break;
        }
        g_thrv[n] = Lmn + (float)(b - 1) * binw - MARGIN;
    }
}

// ---------------- collect candidates ----------------
__global__ __launch_bounds__(128) void collect_kernel() {
    const int n = blockIdx.y, l = blockIdx.x;
    const float t = g_thrv[n];
    const float LR = g_LR[n * HW + l];
    const float Bnd = fmaf(2.0f, g_vmax[n * HW + l], -LR) - g_lcmin[n];
    if (Bnd < t) return;
    const float* row = g_sm + ((size_t)(n * HW + l)) * HW;
    const float* LC = g_LC + n * HW;
    for (int s4 = threadIdx.x * 4; s4 < HW; s4 += 128 * 4) {
        float4 v = *reinterpret_cast<const float4*>(row + s4);
        float4 c = *reinterpret_cast<const float4*>(LC + s4);
        float sc[4];
        sc[0] = fmaf(2.0f, v.x, -LR) - c.x;
        sc[1] = fmaf(2.0f, v.y, -LR) - c.y;
        sc[2] = fmaf(2.0f, v.z, -LR) - c.z;
        sc[3] = fmaf(2.0f, v.w, -LR) - c.w;
#pragma unroll
        for (int q = 0; q < 4; q++) {
            if (sc[q] >= t) {
                int p = atomicAdd(&g_cnt[n], 1);
                if (p < CAP) {
                    g_cv[n * CAP + p] = sc[q];
                    g_ci[n * CAP + p] = l * HW + s4 + q;
                }
            }
        }
    }
}

// ---------------- dedup candidate rows/cols ----------------
__global__ __launch_bounds__(256) void marks_kernel() {
    const int n = blockIdx.y;
    int cnt = g_cnt[n];
    if (cnt > CAP) cnt = CAP;
    for (int j = blockIdx.x * 256 + threadIdx.x; j < cnt; j += 32 * 256) {
        int idx = g_ci[n * CAP + j];
        int l = idx / HW, s = idx % HW;
        if (atomicExch(&g_rflag[n * HW + l], 1) == 0) {
            int p = atomicAdd(&g_rcnt[n], 1);
            if (p < RLCAP) g_rlist[n * RLCAP + p] = l;
        }
        if (atomicExch(&g_cflag[n * HW + s], 1) == 0) {
            int p = atomicAdd(&g_ccnt[n], 1);
            if (p < RLCAP) g_clist[n * RLCAP + p] = s;
        }
    }
}

// ---------------- exact LR for candidate rows ----------------
__global__ __launch_bounds__(128) void exact_row_kernel(const float* __restrict__ x) {
    const int n = blockIdx.y;
    const float* A = x + (size_t)n * CCH * HW;
    const float* B = x + (size_t)(n + NBATCH) * CCH * HW;
    __shared__ float sa[CCH];
    __shared__ float red[128];
    int rc = g_rcnt[n];
    if (rc > RLCAP) rc = RLCAP;
    for (int ri = blockIdx.x; ri < rc; ri += gridDim.x) {
        const int l = g_rlist[n * RLCAP + ri];
        if (threadIdx.x < CCH) sa[threadIdx.x] = A[(size_t)threadIdx.x * HW + l];
        __syncthreads();
        float sum = 0.0f;
        for (int s = threadIdx.x; s < HW; s += 128) {
            float dot = 0.0f;
#pragma unroll 8
            for (int k = 0; k < CCH; k++) dot = fmaf(sa[k], B[(size_t)k * HW + s], dot);
            sum += __expf(dot * (1.0f / 12.8f));
        }
        red[threadIdx.x] = sum;
        __syncthreads();
        for (int o = 64; o > 0; o >>= 1) {
            if (threadIdx.x < o) red[threadIdx.x] += red[threadIdx.x + o];
            __syncthreads();
        }
        if (threadIdx.x == 0) g_LRex[n * HW + l] = logf(red[0]);
        __syncthreads();
    }
}

// ---------------- exact LC for candidate cols ----------------
__global__ __launch_bounds__(128) void exact_col_kernel(const float* __restrict__ x) {
    const int n = blockIdx.y;
    const float* A = x + (size_t)n * CCH * HW;
    const float* B = x + (size_t)(n + NBATCH) * CCH * HW;
    __shared__ float sb[CCH];
    __shared__ float red[128];
    int cc = g_ccnt[n];
    if (cc > RLCAP) cc = RLCAP;
    for (int ci = blockIdx.x; ci < cc; ci += gridDim.x) {
        const int s = g_clist[n * RLCAP + ci];
        if (threadIdx.x < CCH) sb[threadIdx.x] = B[(size_t)threadIdx.x * HW + s];
        __syncthreads();
        float sum = 0.0f;
        for (int l = threadIdx.x; l < HW; l += 128) {
            float dot = 0.0f;
#pragma unroll 8
            for (int k = 0; k < CCH; k++) dot = fmaf(sb[k], A[(size_t)k * HW + l], dot);
            sum += __expf(dot * (1.0f / 12.8f));
        }
        red[threadIdx.x] = sum;
        __syncthreads();
        for (int o = 64; o > 0; o >>= 1) {
            if (threadIdx.x < o) red[threadIdx.x] += red[threadIdx.x + o];
            __syncthreads();
        }
        if (threadIdx.x == 0) g_LCex[n * HW + s] = logf(red[0]);
        __syncthreads();
    }
}

// ---------------- exact rescore (overwrites g_cv with exact scores) ----------------
__global__ __launch_bounds__(256) void rescore_kernel(const float* __restrict__ x) {
    const int n = blockIdx.x;
    const float* A = x + (size_t)n * CCH * HW;
    const float* B = x + (size_t)(n + NBATCH) * CCH * HW;
    int cnt = g_cnt[n];
    if (cnt > CAP) cnt = CAP;
    for (int j = threadIdx.x; j < cnt; j += 256) {
        int idx = g_ci[n * CAP + j];
        int l = idx / HW, s = idx % HW;
        float dot = 0.0f;
#pragma unroll 8
        for (int k = 0; k < CCH; k++)
            dot = fmaf(A[(size_t)k * HW + l], B[(size_t)k * HW + s], dot);
        float v = dot * (1.0f / 12.8f);
        g_cv[n * CAP + j] = fmaf(2.0f, v, -g_LRex[n * HW + l]) - g_LCex[n * HW + s];
    }
}

// ---------------- select top-100 (histogram-refine + bitonic) ----------------
__global__ __launch_bounds__(256) void select_kernel() {
    const int n = blockIdx.x;
    const int tid = threadIdx.x;
    int cnt = g_cnt[n];
    if (cnt > CAP) cnt = CAP;
    float* cv = g_cv + n * CAP;
    int* ci = g_ci + n * CAP;

    __shared__ unsigned long long key[2048];
    __shared__ int hist[2048];
    __shared__ unsigned ssum[256];
    __shared__ float redf[256];
    __shared__ float s_t2;
    __shared__ int s_pos;

    if (cnt <= 2048) {
        for (int i = tid; i < 2048; i += 256)
            key[i] = (i < cnt) ? pack_key(cv[i], ci[i]) : 0ull;
    } else {
        // refine: histogram exact scores in [t, mx], find threshold keeping >=KTOP
        float mx = -CUDART_INF_F;
        for (int j = tid; j < cnt; j += 256) mx = fmaxf(mx, cv[j]);
        redf[tid] = mx;
        __syncthreads();
        for (int o = 128; o > 0; o >>= 1) {
            if (tid < o) redf[tid] = fmaxf(redf[tid], redf[tid + o]);
            __syncthreads();
        }
        const float t = g_thrv[n] - 0.01f;   // exact scores can dip slightly below approx thr
        const float binw = (redf[0] - t) * (1.0f / 2048.0f);
        for (int i = tid; i < 2048; i += 256) { hist[i] = 0; key[i] = 0ull; }
        __syncthreads();
        if (binw < 1e-25f) {
            // degenerate: take first 2048
            for (int i = tid; i < 2048; i += 256)
                if (i < cnt) key[i] = pack_key(cv[i], ci[i]);
            __syncthreads();
        } else {
            const float invw = 1.0f / binw;
            for (int j = tid; j < cnt; j += 256) {
                int b = (int)((cv[j] - t) * invw);
                b = max(0, min(2047, b));
                atomicAdd(&hist[b], 1);
            }
            __syncthreads();
            unsigned csum = 0;
#pragma unroll
            for (int i = 0; i < 8; i++) csum += (unsigned)hist[tid * 8 + i];
            ssum[tid] = csum;
            __syncthreads();
            for (int off = 1; off < 256; off <<= 1) {
                unsigned v = (tid + off < 256) ? ssum[tid + off] : 0u;
                __syncthreads();
                ssum[tid] += v;
                __syncthreads();
            }
            unsigned mine = ssum[tid];
            unsigned nxt = (tid < 255) ? ssum[tid + 1] : 0u;
            if (mine >= KTOP && nxt < KTOP) {
                unsigned cum = nxt;
                int b = tid * 8 + 7;
                for (; b > tid * 8; b--) {
                    cum += (unsigned)hist[b];
                    if (cum >= KTOP) break;
                }
                s_t2 = t + (float)b * binw;
            }
            if (tid == 0) s_pos = 0;
            __syncthreads();
            const float t2 = s_t2;
            for (int j = tid; j < cnt; j += 256) {
                if (cv[j] >= t2) {
                    int p = atomicAdd(&s_pos, 1);
                    if (p < 2048) key[p] = pack_key(cv[j], ci[j]);
                }
            }
            __syncthreads();
        }
    }
    __syncthreads();

    for (int kk = 2; kk <= 2048; kk <<= 1) {
        for (int j = kk >> 1; j > 0; j >>= 1) {
            for (int i = tid; i < 2048; i += 256) {
                int ixj = i ^ j;
                if (ixj > i) {
                    bool dirDesc = ((i & kk) == 0);
                    unsigned long long a = key[i], b = key[ixj];
                    if ((a < b) == dirDesc) { key[i] = b; key[ixj] = a; }
                }
            }
            __syncthreads();
        }
    }
    if (tid < KTOP)
        g_topi[n * KTOP + tid] = (int)(0xFFFFFFFFu - (unsigned)(key[tid] & 0xFFFFFFFFull));
}

// ---------------- embedding ----------------
__global__ __launch_bounds__(128) void prep_kernel(const float* __restrict__ W) {
    const int np = blockIdx.x;
    const int d = threadIdx.x;
    const int n = np & 3;
    const bool side1 = (np >= 4);
    float S = 0.0f, wx = 0.0f, wy = 0.0f;
    for (int k = 0; k < KTOP; k++) {
        int idx = g_topi[n * KTOP + k];
        int r = side1 ? (idx % HW) : (idx / HW);
        float cx = (float)(r % WDIM) / 60.0f;
        float cy = (float)(r / WDIM) / 60.0f;
        float w0 = W[d * (2 * KTOP) + 2 * k];
        float w1 = W[d * (2 * KTOP) + 2 * k + 1];
        S = fmaf(w0, cx, S);
        S = fmaf(w1, cy, S);
        wx += w0; wy += w1;
    }
    g_E[np * CCH + d] = -S;
    if (np == 0) { g_WX[d] = wx; g_WY[d] = wy; }
}

__global__ __launch_bounds__(256) void final_kernel(const float* __restrict__ x,
                                                    const float* __restrict__ bvec,
                                                    float* __restrict__ out) {
    const int d = blockIdx.x;
    const int np = blockIdx.y;
    const float wx = g_WX[d];
    const float wy = g_WY[d];
    const float e = g_E[np * CCH + d] + bvec[d];
    const size_t base = ((size_t)np * CCH + d) * HW;
    for (int p = threadIdx.x; p < HW; p += 256) {
        float gx = (float)(p % WDIM) / 60.0f;
        float gy = (float)(p / WDIM) / 60.0f;
        out[base + p] = x[base + p] + gx * wx + gy * wy + e;
    }
}

// ---------------- launch ----------------
extern "C" void kernel_launch(void* const* d_in, const int* in_sizes, int n_in,
                              void* d_out, int out_size) {
    (void)in_sizes; (void)n_in; (void)out_size;
    const float* x = (const float*)d_in[0];
    const float* W = (const float*)d_in[1];
    const float* b = (const float*)d_in[2];
    float* out = (float*)d_out;

    gemm_kernel<<<dim3(NBX, NBX, NBATCH), 512>>>(x);
    rowfin_kernel<<<dim3(LCPARTS, NBATCH), 256>>>();
    colfin_kernel<<<dim3(LCPARTS, NBATCH), 256>>>();
    bound_kernel<<<NBATCH, 256>>>();
    collect_kernel<<<dim3(HW, NBATCH), 128>>>();
    marks_kernel<<<dim3(32, NBATCH), 256>>>();
    exact_row_kernel<<<dim3(256, NBATCH), 128>>>(x);
    exact_col_kernel<<<dim3(256, NBATCH), 128>>>(x);
    rescore_kernel<<<NBATCH, 256>>>(x);
    select_kernel<<<NBATCH, 256>>>();
    prep_kernel<<<8, 128>>>(W);
    final_kernel<<<dim3(CCH, 8), 256>>>(x, b, out);
}

// round 9
// speedup vs baseline: 2.7950x; 2.7950x over previous
#include <cuda_runtime.h>
#include <math_constants.h>
#include <stdint.h>

#define HW    3600
#define WDIM  60
#define CCH   128
#define NBATCH 4
#define KTOP  100
#define CAP   65536
#define NBX   29          // ceil(3600/128)
#define BK    16
#define SPAD  136         // smem row pitch (conflict-free fragment loads)
#define LCPARTS 15

// ---------------- device scratch ----------------
__device__ float g_sm[(size_t)NBATCH * HW * HW];   // 207 MB
__device__ float g_rp[NBATCH * NBX * HW];
__device__ float g_cp[NBATCH * NBX * HW];
__device__ float g_vp[NBATCH * NBX * HW];
__device__ float g_LR[NBATCH * HW];
__device__ float g_LC[NBATCH * HW];
__device__ float g_vmax[NBATCH * HW];
__device__ float g_lcmin_part[NBATCH * LCPARTS];
__device__ float g_lcmax_part[NBATCH * LCPARTS];
__device__ float g_thrv[NBATCH];
__device__ float g_lcmin[NBATCH];
__device__ int   g_cnt[NBATCH];
__device__ float g_cv[NBATCH * CAP];
__device__ int   g_ci[NBATCH * CAP];
__device__ int   g_topi[NBATCH * KTOP];
__device__ float g_E[8 * CCH];
__device__ float g_WX[CCH];
__device__ float g_WY[CCH];

// ---------------- helpers ----------------
__device__ __forceinline__ void cp16(float* dst_smem, const float* src, bool ok) {
    unsigned d = (unsigned)__cvta_generic_to_shared(dst_smem);
    int sz = ok ? 16 : 0;
    asm volatile("cp.async.ca.shared.global [%0], [%1], 16, %2;\n" :: "r"(d), "l"(src), "r"(sz));
}
__device__ __forceinline__ void cp_commit() { asm volatile("cp.async.commit_group;\n"); }
__device__ __forceinline__ void cp_wait0()  { asm volatile("cp.async.wait_group 0;\n"); }

__device__ __forceinline__ void mma_tf32(float c[4], const unsigned a[4], const unsigned b[2]) {
    asm volatile(
        "mma.sync.aligned.m16n8k8.row.col.f32.tf32.tf32.f32 "
        "{%0,%1,%2,%3}, {%4,%5,%6,%7}, {%8,%9}, {%0,%1,%2,%3};"
        : "+f"(c[0]), "+f"(c[1]), "+f"(c[2]), "+f"(c[3])
        : "r"(a[0]), "r"(a[1]), "r"(a[2]), "r"(a[3]), "r"(b[0]), "r"(b[1]));
}

__device__ __forceinline__ unsigned mono_bits(float f) {
    unsigned b = __float_as_uint(f);
    return (b & 0x80000000u) ? ~b : (b | 0x80000000u);
}

// split fp32 -> tf32 hi (truncated) + lo (exact remainder)
__device__ __forceinline__ void tf32split(float a, unsigned& hi, unsigned& lo) {
    hi = __float_as_uint(a) & 0xFFFFE000u;
    lo = __float_as_uint(a - __uint_as_float(hi));
}

// ---------------- GEMM (tf32 x3 mma, term-major issue order) + fused exp-stats ----------------
// 512 threads, 16 warps in 4x4 grid, warp tile 32x32, block tile 128x128.
__global__ __launch_bounds__(512, 1) void gemm_kernel(const float* __restrict__ x) {
    __shared__ float As[2][BK][SPAD];
    __shared__ float Bs[2][BK][SPAD];
    __shared__ float s_rs[4][128];
    __shared__ float s_rm[4][128];
    __shared__ float s_cs[4][128];

    const int n  = blockIdx.z;
    const int l0 = blockIdx.y * 128;
    const int s0 = blockIdx.x * 128;
    const float* A = x + (size_t)n * CCH * HW;
    const float* B = x + (size_t)(n + NBATCH) * CCH * HW;
    const int tid = threadIdx.x;
    const int lane = tid & 31;
    const int wid = tid >> 5;
    const int g = lane >> 2, tig = lane & 3;
    const int wm = wid & 3, wn = wid >> 2;
    const int rb = wm * 32, cb = wn * 32;

    float acc[2][4][4];
#pragma unroll
    for (int mi = 0; mi < 2; mi++)
#pragma unroll
        for (int ni = 0; ni < 4; ni++)
#pragma unroll
            for (int q = 0; q < 4; q++) acc[mi][ni][q] = 0.0f;

    {
        const int d = tid >> 5;
        const int c4 = lane << 2;
        int colA = l0 + c4; bool okA = colA < HW;
        cp16(&As[0][d][c4], A + (size_t)d * HW + (okA ? colA : 0), okA);
        int colB = s0 + c4; bool okB = colB < HW;
        cp16(&Bs[0][d][c4], B + (size_t)d * HW + (okB ? colB : 0), okB);
    }
    cp_commit();

    for (int c = 0; c < CCH / BK; c++) {
        cp_wait0();
        __syncthreads();
        if (c < CCH / BK - 1) {
            const int kc = c + 1, st = (c + 1) & 1;
            const int d = tid >> 5;
            const int c4 = lane << 2;
            int colA = l0 + c4; bool okA = colA < HW;
            cp16(&As[st][d][c4], A + (size_t)(kc * BK + d) * HW + (okA ? colA : 0), okA);
            int colB = s0 + c4; bool okB = colB < HW;
            cp16(&Bs[st][d][c4], B + (size_t)(kc * BK + d) * HW + (okB ? colB : 0), okB);
            cp_commit();
        }
        const int st = c & 1;
#pragma unroll
        for (int ks = 0; ks < BK; ks += 8) {
            const int k0 = ks + tig;
            unsigned ah[2][4], al[2][4], bh[4][2], bl[4][2];
#pragma unroll
            for (int mi = 0; mi < 2; mi++) {
                const int m = rb + mi * 16 + g;
                tf32split(As[st][k0][m],         ah[mi][0], al[mi][0]);
                tf32split(As[st][k0][m + 8],     ah[mi][1], al[mi][1]);
                tf32split(As[st][k0 + 4][m],     ah[mi][2], al[mi][2]);
                tf32split(As[st][k0 + 4][m + 8], ah[mi][3], al[mi][3]);
            }
#pragma unroll
            for (int ni = 0; ni < 4; ni++) {
                const int nn = cb + ni * 8 + g;
                tf32split(Bs[st][k0][nn],     bh[ni][0], bl[ni][0]);
                tf32split(Bs[st][k0 + 4][nn], bh[ni][1], bl[ni][1]);
            }
            // term-major issue: consecutive mma hit distinct accumulators
#pragma unroll
            for (int mi = 0; mi < 2; mi++)
#pragma unroll
                for (int ni = 0; ni < 4; ni++)
                    mma_tf32(acc[mi][ni], ah[mi], bl[ni]);
#pragma unroll
            for (int mi = 0; mi < 2; mi++)
#pragma unroll
                for (int ni = 0; ni < 4; ni++)
                    mma_tf32(acc[mi][ni], al[mi], bh[ni]);
#pragma unroll
            for (int mi = 0; mi < 2; mi++)
#pragma unroll
                for (int ni = 0; ni < 4; ni++)
                    mma_tf32(acc[mi][ni], ah[mi], bh[ni]);
        }
    }

    const float inv = 1.0f / 12.8f;
    float rsum[2][2], rmax[2][2], csum[4][2];
#pragma unroll
    for (int i = 0; i < 2; i++)
#pragma unroll
        for (int r = 0; r < 2; r++) { rsum[i][r] = 0.0f; rmax[i][r] = -CUDART_INF_F; }
#pragma unroll
    for (int i = 0; i < 4; i++) { csum[i][0] = 0.0f; csum[i][1] = 0.0f; }

#pragma unroll
    for (int mi = 0; mi < 2; mi++) {
        const int row0 = l0 + rb + mi * 16 + g;
        const int row1 = row0 + 8;
        const bool rv0 = row0 < HW, rv1 = row1 < HW;
        float* orow0 = g_sm + ((size_t)(n * HW + row0)) * HW;
        float* orow1 = g_sm + ((size_t)(n * HW + row1)) * HW;
#pragma unroll
        for (int ni = 0; ni < 4; ni++) {
            const int sc0 = s0 + cb + ni * 8 + tig * 2;
            const bool cv0 = sc0 < HW, cv1 = (sc0 + 1) < HW;
            float v0 = acc[mi][ni][0] * inv;
            float v1 = acc[mi][ni][1] * inv;
            float v2 = acc[mi][ni][2] * inv;
            float v3 = acc[mi][ni][3] * inv;
            if (rv0 && cv0) *reinterpret_cast<float2*>(orow0 + sc0) = make_float2(v0, v1);
            if (rv1 && cv0) *reinterpret_cast<float2*>(orow1 + sc0) = make_float2(v2, v3);
            float e0 = cv0 ? __expf(v0) : 0.0f;
            float e1 = cv1 ? __expf(v1) : 0.0f;
            float e2 = cv0 ? __expf(v2) : 0.0f;
            float e3 = cv1 ? __expf(v3) : 0.0f;
            rsum[mi][0] += e0 + e1;
            rsum[mi][1] += e2 + e3;
            rmax[mi][0] = fmaxf(rmax[mi][0], fmaxf(cv0 ? v0 : -CUDART_INF_F, cv1 ? v1 : -CUDART_INF_F));
            rmax[mi][1] = fmaxf(rmax[mi][1], fmaxf(cv0 ? v2 : -CUDART_INF_F, cv1 ? v3 : -CUDART_INF_F));
            csum[ni][0] += (rv0 ? e0 : 0.0f) + (rv1 ? e2 : 0.0f);
            csum[ni][1] += (rv0 ? e1 : 0.0f) + (rv1 ? e3 : 0.0f);
        }
    }

#pragma unroll
    for (int m = 1; m < 4; m <<= 1) {
#pragma unroll
        for (int mi = 0; mi < 2; mi++)
#pragma unroll
            for (int r = 0; r < 2; r++) {
                rsum[mi][r] += __shfl_xor_sync(0xffffffffu, rsum[mi][r], m);
                rmax[mi][r] = fmaxf(rmax[mi][r], __shfl_xor_sync(0xffffffffu, rmax[mi][r], m));
            }
    }
    if (tig == 0) {
#pragma unroll
        for (int mi = 0; mi < 2; mi++) {
            const int rr = rb + mi * 16 + g;
            s_rs[wn][rr] = rsum[mi][0];
            s_rs[wn][rr + 8] = rsum[mi][1];
            s_rm[wn][rr] = rmax[mi][0];
            s_rm[wn][rr + 8] = rmax[mi][1];
        }
    }
#pragma unroll
    for (int m = 4; m < 32; m <<= 1) {
#pragma unroll
        for (int ni = 0; ni < 4; ni++)
#pragma unroll
            for (int q = 0; q < 2; q++)
                csum[ni][q] += __shfl_xor_sync(0xffffffffu, csum[ni][q], m);
    }
    if (g == 0) {
#pragma unroll
        for (int ni = 0; ni < 4; ni++) {
            s_cs[wm][cb + ni * 8 + tig * 2]     = csum[ni][0];
            s_cs[wm][cb + ni * 8 + tig * 2 + 1] = csum[ni][1];
        }
    }
    __syncthreads();
    if (tid < 128) {
        float rs = 0.0f, rm = -CUDART_INF_F;
#pragma unroll
        for (int w = 0; w < 4; w++) { rs += s_rs[w][tid]; rm = fmaxf(rm, s_rm[w][tid]); }
        if (l0 + tid < HW) {
            g_rp[(n * NBX + blockIdx.x) * HW + l0 + tid] = rs;
            g_vp[(n * NBX + blockIdx.x) * HW + l0 + tid] = rm;
        }
        float cs = 0.0f;
#pragma unroll
        for (int w = 0; w < 4; w++) cs += s_cs[w][tid];
        if (s0 + tid < HW)
            g_cp[(n * NBX + blockIdx.y) * HW + s0 + tid] = cs;
    }
}

// ---------------- merge: LR, vmax ----------------
__global__ __launch_bounds__(256) void rowfin_kernel() {
    const int n = blockIdx.y;
    const int l = blockIdx.x * 256 + threadIdx.x;
    if (l >= HW) return;
    float s = 0.0f, m = -CUDART_INF_F;
#pragma unroll
    for (int b = 0; b < NBX; b++) {
        s += g_rp[(n * NBX + b) * HW + l];
        m = fmaxf(m, g_vp[(n * NBX + b) * HW + l]);
    }
    g_LR[n * HW + l] = logf(s);
    g_vmax[n * HW + l] = m;
}

// ---------------- merge: LC + per-block min/max ----------------
__global__ __launch_bounds__(256) void colfin_kernel() {
    const int n = blockIdx.y;
    const int s = blockIdx.x * 256 + threadIdx.x;
    __shared__ float mn[256], mx[256];
    float lo = CUDART_INF_F, hi = -CUDART_INF_F;
    if (s < HW) {
        float acc = 0.0f;
#pragma unroll
        for (int b = 0; b < NBX; b++) acc += g_cp[(n * NBX + b) * HW + s];
        float v = logf(acc);
        g_LC[n * HW + s] = v;
        lo = v; hi = v;
    }
    const int tid = threadIdx.x;
    mn[tid] = lo; mx[tid] = hi;
    __syncthreads();
    for (int o = 128; o > 0; o >>= 1) {
        if (tid < o) {
            mn[tid] = fminf(mn[tid], mn[tid + o]);
            mx[tid] = fmaxf(mx[tid], mx[tid + o]);
        }
        __syncthreads();
    }
    if (tid == 0) {
        g_lcmin_part[n * LCPARTS + blockIdx.x] = mn[0];
        g_lcmax_part[n * LCPARTS + blockIdx.x] = mx[0];
    }
}

// ---------------- threshold from per-row score lower bounds ----------------
__global__ __launch_bounds__(256) void bound_kernel() {
    const int n = blockIdx.x;
    const int tid = threadIdx.x;
    __shared__ float s_lcmax;
    __shared__ float red1[256], red2[256];
    __shared__ int hist[2048];
    __shared__ unsigned ssum[256];
    __shared__ float s_lmn, s_lmx;

    if (tid == 0) {
        float mn = CUDART_INF_F, mx = -CUDART_INF_F;
        for (int i = 0; i < LCPARTS; i++) {
            mn = fminf(mn, g_lcmin_part[n * LCPARTS + i]);
            mx = fmaxf(mx, g_lcmax_part[n * LCPARTS + i]);
        }
        g_lcmin[n] = mn;
        s_lcmax = mx;
        g_cnt[n] = 0;
    }
    __syncthreads();
    const float lcmax = s_lcmax;

    float lmn = CUDART_INF_F, lmx = -CUDART_INF_F;
    for (int l = tid; l < HW; l += 256) {
        float L = fmaf(2.0f, g_vmax[n * HW + l], -g_LR[n * HW + l]) - lcmax;
        lmn = fminf(lmn, L); lmx = fmaxf(lmx, L);
    }
    red1[tid] = lmn; red2[tid] = lmx;
    __syncthreads();
    for (int o = 128; o > 0; o >>= 1) {
        if (tid < o) {
            red1[tid] = fminf(red1[tid], red1[tid + o]);
            red2[tid] = fmaxf(red2[tid], red2[tid + o]);
        }
        __syncthreads();
    }
    if (tid == 0) { s_lmn = red1[0]; s_lmx = red2[0]; }
    __syncthreads();
    const float Lmn = s_lmn;
    const float binw = (s_lmx - Lmn) * (1.0f / 2048.0f);
    if (binw < 1e-30f) {
        if (tid == 0) g_thrv[n] = Lmn;
        return;
    }
    for (int i = tid; i < 2048; i += 256) hist[i] = 0;
    __syncthreads();
    for (int l = tid; l < HW; l += 256) {
        float L = fmaf(2.0f, g_vmax[n * HW + l], -g_LR[n * HW + l]) - lcmax;
        int b = (int)((L - Lmn) / binw);
        b = max(0, min(2047, b));
        atomicAdd(&hist[b], 1);
    }
    __syncthreads();
    unsigned csum = 0;
#pragma unroll
    for (int i = 0; i < 8; i++) csum += (unsigned)hist[tid * 8 + i];
    ssum[tid] = csum;
    __syncthreads();
    for (int off = 1; off < 256; off <<= 1) {
        unsigned v = (tid + off < 256) ? ssum[tid + off] : 0u;
        __syncthreads();
        ssum[tid] += v;
        __syncthreads();
    }
    unsigned mine = ssum[tid];
    unsigned nxt = (tid < 255) ? ssum[tid + 1] : 0u;
    if (mine >= KTOP && nxt < KTOP) {
        unsigned cum = nxt;
        int b = tid * 8 + 7;
        for (; b > tid * 8; b--) {
            cum += (unsigned)hist[b];
            if (cum >= KTOP) break;
        }
        g_thrv[n] = Lmn + (float)(b - 1) * binw;   // one-bin safety margin
    }
}

// ---------------- collect candidates (only flagged rows) ----------------
__global__ __launch_bounds__(128) void collect_kernel() {
    const int n = blockIdx.y, l = blockIdx.x;
    const float t = g_thrv[n];
    const float LR = g_LR[n * HW + l];
    const float Bnd = fmaf(2.0f, g_vmax[n * HW + l], -LR) - g_lcmin[n];
    if (Bnd < t) return;
    const float* row = g_sm + ((size_t)(n * HW + l)) * HW;
    const float* LC = g_LC + n * HW;
    for (int s4 = threadIdx.x * 4; s4 < HW; s4 += 128 * 4) {
        float4 v = *reinterpret_cast<const float4*>(row + s4);
        float4 c = *reinterpret_cast<const float4*>(LC + s4);
        float sc[4];
        sc[0] = fmaf(2.0f, v.x, -LR) - c.x;
        sc[1] = fmaf(2.0f, v.y, -LR) - c.y;
        sc[2] = fmaf(2.0f, v.z, -LR) - c.z;
        sc[3] = fmaf(2.0f, v.w, -LR) - c.w;
#pragma unroll
        for (int q = 0; q < 4; q++) {
            if (sc[q] >= t) {
                int p = atomicAdd(&g_cnt[n], 1);
                if (p < CAP) {
                    g_cv[n * CAP + p] = sc[q];
                    g_ci[n * CAP + p] = l * HW + s4 + q;
                }
            }
        }
    }
}

// ---------------- top-100: smem bitonic sort on packed keys ----------------
__global__ __launch_bounds__(256) void select_kernel() {
    const int n = blockIdx.x;
    const int tid = threadIdx.x;
    int cnt = g_cnt[n];
    if (cnt > CAP) cnt = CAP;
    float* cv = g_cv + n * CAP;
    int* ci = g_ci + n * CAP;

    if (cnt <= 2048) {
        __shared__ unsigned long long key[2048];
        for (int i = tid; i < 2048; i += 256) {
            unsigned long long k = 0ull;
            if (i < cnt)
                k = ((unsigned long long)mono_bits(cv[i]) << 32) |
                    (unsigned long long)(0xFFFFFFFFu - (unsigned)ci[i]);
            key[i] = k;
        }
        __syncthreads();
        for (int kk = 2; kk <= 2048; kk <<= 1) {
            for (int j = kk >> 1; j > 0; j >>= 1) {
                for (int i = tid; i < 2048; i += 256) {
                    int ixj = i ^ j;
                    if (ixj > i) {
                        bool dirDesc = ((i & kk) == 0);
                        unsigned long long a = key[i], b = key[ixj];
                        if ((a < b) == dirDesc) { key[i] = b; key[ixj] = a; }
                    }
                }
                __syncthreads();
            }
        }
        if (tid < KTOP)
            g_topi[n * KTOP + tid] = (int)(0xFFFFFFFFu - (unsigned)(key[tid] & 0xFFFFFFFFull));
        return;
    }

    // fallback: iterative argmax
    __shared__ float sv[256];
    __shared__ int si[256];
    __shared__ int sp[256];
    for (int k = 0; k < KTOP; k++) {
        float bv = -CUDART_INF_F; int bi = 0x7FFFFFFF; int bp = -1;
        for (int j = tid; j < cnt; j += 256) {
            float v = cv[j]; int idx = ci[j];
            if (v > bv || (v == bv && idx < bi)) { bv = v; bi = idx; bp = j; }
        }
        sv[tid] = bv; si[tid] = bi; sp[tid] = bp;
        __syncthreads();
        for (int o = 128; o > 0; o >>= 1) {
            if (tid < o) {
                if (sv[tid + o] > sv[tid] || (sv[tid + o] == sv[tid] && si[tid + o] < si[tid])) {
                    sv[tid] = sv[tid + o]; si[tid] = si[tid + o]; sp[tid] = sp[tid + o];
                }
            }
            __syncthreads();
        }
        if (tid == 0) {
            g_topi[n * KTOP + k] = si[0];
            if (sp[0] >= 0) cv[sp[0]] = -CUDART_INF_F;
        }
        __syncthreads();
    }
}

// ---------------- embedding ----------------
__global__ __launch_bounds__(128) void prep_kernel(const float* __restrict__ W) {
    const int np = blockIdx.x;
    const int d = threadIdx.x;
    const int n = np & 3;
    const bool side1 = (np >= 4);
    float S = 0.0f, wx = 0.0f, wy = 0.0f;
    for (int k = 0; k < KTOP; k++) {
        int idx = g_topi[n * KTOP + k];
        int r = side1 ? (idx % HW) : (idx / HW);
        float cx = (float)(r % WDIM) / 60.0f;
        float cy = (float)(r / WDIM) / 60.0f;
        float w0 = W[d * (2 * KTOP) + 2 * k];
        float w1 = W[d * (2 * KTOP) + 2 * k + 1];
        S = fmaf(w0, cx, S);
        S = fmaf(w1, cy, S);
        wx += w0; wy += w1;
    }
    g_E[np * CCH + d] = -S;
    if (np == 0) { g_WX[d] = wx; g_WY[d] = wy; }
}

__global__ __launch_bounds__(256) void final_kernel(const float* __restrict__ x,
                                                    const float* __restrict__ bvec,
                                                    float* __restrict__ out) {
    const int d = blockIdx.x;
    const int np = blockIdx.y;
    const float wx = g_WX[d];
    const float wy = g_WY[d];
    const float e = g_E[np * CCH + d] + bvec[d];
    const size_t base = ((size_t)np * CCH + d) * HW;
    for (int p = threadIdx.x; p < HW; p += 256) {
        float gx = (float)(p % WDIM) / 60.0f;
        float gy = (float)(p / WDIM) / 60.0f;
        out[base + p] = x[base + p] + gx * wx + gy * wy + e;
    }
}

// ---------------- launch ----------------
extern "C" void kernel_launch(void* const* d_in, const int* in_sizes, int n_in,
                              void* d_out, int out_size) {
    (void)in_sizes; (void)n_in; (void)out_size;
    const float* x = (const float*)d_in[0];
    const float* W = (const float*)d_in[1];
    const float* b = (const float*)d_in[2];
    float* out = (float*)d_out;

    gemm_kernel<<<dim3(NBX, NBX, NBATCH), 512>>>(x);
    rowfin_kernel<<<dim3(LCPARTS, NBATCH), 256>>>();
    colfin_kernel<<<dim3(LCPARTS, NBATCH), 256>>>();
    bound_kernel<<<NBATCH, 256>>>();
    collect_kernel<<<dim3(HW, NBATCH), 128>>>();
    select_kernel<<<NBATCH, 256>>>();
    prep_kernel<<<8, 128>>>(W);
    final_kernel<<<dim3(CCH, 8), 256>>>(x, b, out);
}

// round 10
// speedup vs baseline: 3.2959x; 1.1792x over previous
#include <cuda_runtime.h>
#include <cuda_fp16.h>
#include <math_constants.h>
#include <stdint.h>

#define HW    3600
#define WDIM  60
#define CCH   128
#define NBATCH 4
#define KTOP  100
#define CAP   65536
#define NBX   29          // ceil(3600/128)
#define LCPARTS 15
#define SPH   136         // half2 row pitch (conflict-free)

// ---------------- device scratch ----------------
__device__ float g_sm[(size_t)NBATCH * HW * HW];   // 207 MB
__device__ float g_rp[NBATCH * NBX * HW];
__device__ float g_cp[NBATCH * NBX * HW];
__device__ float g_vp[NBATCH * NBX * HW];
__device__ float g_LR[NBATCH * HW];
__device__ float g_LC[NBATCH * HW];
__device__ float g_vmax[NBATCH * HW];
__device__ float g_lcmin_part[NBATCH * LCPARTS];
__device__ float g_lcmax_part[NBATCH * LCPARTS];
__device__ float g_thrv[NBATCH];
__device__ float g_lcmin[NBATCH];
__device__ int   g_cnt[NBATCH];
__device__ float g_cv[NBATCH * CAP];
__device__ int   g_ci[NBATCH * CAP];
__device__ int   g_topi[NBATCH * KTOP];
__device__ float g_E[8 * CCH];
__device__ float g_WX[CCH];
__device__ float g_WY[CCH];

// ---------------- helpers ----------------
__device__ __forceinline__ void mma_f16(float c[4], const unsigned a[4], const unsigned b[2]) {
    asm volatile(
        "mma.sync.aligned.m16n8k16.row.col.f32.f16.f16.f32 "
        "{%0,%1,%2,%3}, {%4,%5,%6,%7}, {%8,%9}, {%0,%1,%2,%3};"
        : "+f"(c[0]), "+f"(c[1]), "+f"(c[2]), "+f"(c[3])
        : "r"(a[0]), "r"(a[1]), "r"(a[2]), "r"(a[3]), "r"(b[0]), "r"(b[1]));
}
__device__ __forceinline__ unsigned mono_bits(float f) {
    unsigned b = __float_as_uint(f);
    return (b & 0x80000000u) ? ~b : (b | 0x80000000u);
}
__device__ __forceinline__ unsigned h2u(__half2 h) {
    return *reinterpret_cast<unsigned*>(&h);
}

// ---------------- GEMM (fp16 x3 split, m16n8k16) + fused exp-stats ----------------
// 512 threads, 16 warps in 4x4 grid, warp tile 32x32, block tile 128x128, K chunk 16.
__global__ __launch_bounds__(512, 1) void gemm_kernel(const float* __restrict__ x) {
    __shared__ __align__(16) __half2 Ah[2][8][SPH];
    __shared__ __align__(16) __half2 Al[2][8][SPH];
    __shared__ __align__(16) __half2 Bh[2][8][SPH];
    __shared__ __align__(16) __half2 Bl[2][8][SPH];
    __shared__ float s_rs[4][128];
    __shared__ float s_rm[4][128];
    __shared__ float s_cs[4][128];

    const int n  = blockIdx.z;
    const int l0 = blockIdx.y * 128;
    const int s0 = blockIdx.x * 128;
    const float* A = x + (size_t)n * CCH * HW;
    const float* B = x + (size_t)(n + NBATCH) * CCH * HW;
    const int tid = threadIdx.x;
    const int lane = tid & 31;
    const int wid = tid >> 5;
    const int g = lane >> 2, tig = lane & 3;
    const int wm = wid & 3, wn = wid >> 2;
    const int rb = wm * 32, cb = wn * 32;

    // loader role: tid<256 -> A plane, else B plane
    const int side = tid >> 8;
    const int slot = tid & 255;
    const int kp = slot >> 5;           // 0..7 (k pair within chunk)
    const int m0 = (slot & 31) << 2;    // 0..124
    const float* P = side ? B : A;
    const int base0 = side ? s0 : l0;
    const bool okc = (base0 + m0) < HW;

    float acc[2][4][4];
#pragma unroll
    for (int mi = 0; mi < 2; mi++)
#pragma unroll
        for (int ni = 0; ni < 4; ni++)
#pragma unroll
            for (int q = 0; q < 4; q++) acc[mi][ni][q] = 0.0f;

    float4 r0, r1;
    // LDG chunk 0
    {
        const int d = kp * 2;
        r0 = okc ? *reinterpret_cast<const float4*>(P + (size_t)d * HW + base0 + m0)
                 : make_float4(0.f, 0.f, 0.f, 0.f);
        r1 = okc ? *reinterpret_cast<const float4*>(P + (size_t)(d + 1) * HW + base0 + m0)
                 : make_float4(0.f, 0.f, 0.f, 0.f);
    }
    // convert + STS stage 0
    {
        __half2 h0 = __floats2half2_rn(r0.x, r1.x);
        __half2 h1 = __floats2half2_rn(r0.y, r1.y);
        __half2 h2 = __floats2half2_rn(r0.z, r1.z);
        __half2 h3 = __floats2half2_rn(r0.w, r1.w);
        float2 b0 = __half22float2(h0), b1 = __half22float2(h1);
        float2 b2 = __half22float2(h2), b3 = __half22float2(h3);
        __half2 l0h = __floats2half2_rn(r0.x - b0.x, r1.x - b0.y);
        __half2 l1h = __floats2half2_rn(r0.y - b1.x, r1.y - b1.y);
        __half2 l2h = __floats2half2_rn(r0.z - b2.x, r1.z - b2.y);
        __half2 l3h = __floats2half2_rn(r0.w - b3.x, r1.w - b3.y);
        __half2* dh = side ? &Bh[0][kp][m0] : &Ah[0][kp][m0];
        __half2* dl = side ? &Bl[0][kp][m0] : &Al[0][kp][m0];
        *reinterpret_cast<uint4*>(dh) = make_uint4(h2u(h0), h2u(h1), h2u(h2), h2u(h3));
        *reinterpret_cast<uint4*>(dl) = make_uint4(h2u(l0h), h2u(l1h), h2u(l2h), h2u(l3h));
    }
    __syncthreads();

    for (int c = 0; c < 8; c++) {
        const int st = c & 1;
        if (c < 7) {
            const int d = (c + 1) * 16 + kp * 2;
            r0 = okc ? *reinterpret_cast<const float4*>(P + (size_t)d * HW + base0 + m0)
                     : make_float4(0.f, 0.f, 0.f, 0.f);
            r1 = okc ? *reinterpret_cast<const float4*>(P + (size_t)(d + 1) * HW + base0 + m0)
                     : make_float4(0.f, 0.f, 0.f, 0.f);
        }
        // fragments
        unsigned ah[2][4], al[2][4], bh[4][2], bl[4][2];
#pragma unroll
        for (int mi = 0; mi < 2; mi++) {
            const int mp = rb + mi * 16 + g;
            ah[mi][0] = h2u(Ah[st][tig][mp]);
            ah[mi][1] = h2u(Ah[st][tig][mp + 8]);
            ah[mi][2] = h2u(Ah[st][tig + 4][mp]);
            ah[mi][3] = h2u(Ah[st][tig + 4][mp + 8]);
            al[mi][0] = h2u(Al[st][tig][mp]);
            al[mi][1] = h2u(Al[st][tig][mp + 8]);
            al[mi][2] = h2u(Al[st][tig + 4][mp]);
            al[mi][3] = h2u(Al[st][tig + 4][mp + 8]);
        }
#pragma unroll
        for (int ni = 0; ni < 4; ni++) {
            const int np = cb + ni * 8 + g;
            bh[ni][0] = h2u(Bh[st][tig][np]);
            bh[ni][1] = h2u(Bh[st][tig + 4][np]);
            bl[ni][0] = h2u(Bl[st][tig][np]);
            bl[ni][1] = h2u(Bl[st][tig + 4][np]);
        }
#pragma unroll
        for (int mi = 0; mi < 2; mi++)
#pragma unroll
            for (int ni = 0; ni < 4; ni++)
                mma_f16(acc[mi][ni], ah[mi], bl[ni]);
#pragma unroll
        for (int mi = 0; mi < 2; mi++)
#pragma unroll
            for (int ni = 0; ni < 4; ni++)
                mma_f16(acc[mi][ni], al[mi], bh[ni]);
#pragma unroll
        for (int mi = 0; mi < 2; mi++)
#pragma unroll
            for (int ni = 0; ni < 4; ni++)
                mma_f16(acc[mi][ni], ah[mi], bh[ni]);

        if (c < 7) {
            const int st2 = (c + 1) & 1;
            __half2 h0 = __floats2half2_rn(r0.x, r1.x);
            __half2 h1 = __floats2half2_rn(r0.y, r1.y);
            __half2 h2 = __floats2half2_rn(r0.z, r1.z);
            __half2 h3 = __floats2half2_rn(r0.w, r1.w);
            float2 b0 = __half22float2(h0), b1 = __half22float2(h1);
            float2 b2 = __half22float2(h2), b3 = __half22float2(h3);
            __half2 l0h = __floats2half2_rn(r0.x - b0.x, r1.x - b0.y);
            __half2 l1h = __floats2half2_rn(r0.y - b1.x, r1.y - b1.y);
            __half2 l2h = __floats2half2_rn(r0.z - b2.x, r1.z - b2.y);
            __half2 l3h = __floats2half2_rn(r0.w - b3.x, r1.w - b3.y);
            __half2* dh = side ? &Bh[st2][kp][m0] : &Ah[st2][kp][m0];
            __half2* dl = side ? &Bl[st2][kp][m0] : &Al[st2][kp][m0];
            *reinterpret_cast<uint4*>(dh) = make_uint4(h2u(h0), h2u(h1), h2u(h2), h2u(h3));
            *reinterpret_cast<uint4*>(dl) = make_uint4(h2u(l0h), h2u(l1h), h2u(l2h), h2u(l3h));
        }
        __syncthreads();
    }

    // ---- epilogue: scale, store, exp stats (identical to R4) ----
    const float inv = 1.0f / 12.8f;
    float rsum[2][2], rmax[2][2], csum[4][2];
#pragma unroll
    for (int i = 0; i < 2; i++)
#pragma unroll
        for (int r = 0; r < 2; r++) { rsum[i][r] = 0.0f; rmax[i][r] = -CUDART_INF_F; }
#pragma unroll
    for (int i = 0; i < 4; i++) { csum[i][0] = 0.0f; csum[i][1] = 0.0f; }

#pragma unroll
    for (int mi = 0; mi < 2; mi++) {
        const int row0 = l0 + rb + mi * 16 + g;
        const int row1 = row0 + 8;
        const bool rv0 = row0 < HW, rv1 = row1 < HW;
        float* orow0 = g_sm + ((size_t)(n * HW + row0)) * HW;
        float* orow1 = g_sm + ((size_t)(n * HW + row1)) * HW;
#pragma unroll
        for (int ni = 0; ni < 4; ni++) {
            const int sc0 = s0 + cb + ni * 8 + tig * 2;
            const bool cv0 = sc0 < HW, cv1 = (sc0 + 1) < HW;
            float v0 = acc[mi][ni][0] * inv;
            float v1 = acc[mi][ni][1] * inv;
            float v2 = acc[mi][ni][2] * inv;
            float v3 = acc[mi][ni][3] * inv;
            if (rv0 && cv0) *reinterpret_cast<float2*>(orow0 + sc0) = make_float2(v0, v1);
            if (rv1 && cv0) *reinterpret_cast<float2*>(orow1 + sc0) = make_float2(v2, v3);
            float e0 = cv0 ? __expf(v0) : 0.0f;
            float e1 = cv1 ? __expf(v1) : 0.0f;
            float e2 = cv0 ? __expf(v2) : 0.0f;
            float e3 = cv1 ? __expf(v3) : 0.0f;
            rsum[mi][0] += e0 + e1;
            rsum[mi][1] += e2 + e3;
            rmax[mi][0] = fmaxf(rmax[mi][0], fmaxf(cv0 ? v0 : -CUDART_INF_F, cv1 ? v1 : -CUDART_INF_F));
            rmax[mi][1] = fmaxf(rmax[mi][1], fmaxf(cv0 ? v2 : -CUDART_INF_F, cv1 ? v3 : -CUDART_INF_F));
            csum[ni][0] += (rv0 ? e0 : 0.0f) + (rv1 ? e2 : 0.0f);
            csum[ni][1] += (rv0 ? e1 : 0.0f) + (rv1 ? e3 : 0.0f);
        }
    }

#pragma unroll
    for (int m = 1; m < 4; m <<= 1) {
#pragma unroll
        for (int mi = 0; mi < 2; mi++)
#pragma unroll
            for (int r = 0; r < 2; r++) {
                rsum[mi][r] += __shfl_xor_sync(0xffffffffu, rsum[mi][r], m);
                rmax[mi][r] = fmaxf(rmax[mi][r], __shfl_xor_sync(0xffffffffu, rmax[mi][r], m));
            }
    }
    if (tig == 0) {
#pragma unroll
        for (int mi = 0; mi < 2; mi++) {
            const int rr = rb + mi * 16 + g;
            s_rs[wn][rr] = rsum[mi][0];
            s_rs[wn][rr + 8] = rsum[mi][1];
            s_rm[wn][rr] = rmax[mi][0];
            s_rm[wn][rr + 8] = rmax[mi][1];
        }
    }
#pragma unroll
    for (int m = 4; m < 32; m <<= 1) {
#pragma unroll
        for (int ni = 0; ni < 4; ni++)
#pragma unroll
            for (int q = 0; q < 2; q++)
                csum[ni][q] += __shfl_xor_sync(0xffffffffu, csum[ni][q], m);
    }
    if (g == 0) {
#pragma unroll
        for (int ni = 0; ni < 4; ni++) {
            s_cs[wm][cb + ni * 8 + tig * 2]     = csum[ni][0];
            s_cs[wm][cb + ni * 8 + tig * 2 + 1] = csum[ni][1];
        }
    }
    __syncthreads();
    if (tid < 128) {
        float rs = 0.0f, rm = -CUDART_INF_F;
#pragma unroll
        for (int w = 0; w < 4; w++) { rs += s_rs[w][tid]; rm = fmaxf(rm, s_rm[w][tid]); }
        if (l0 + tid < HW) {
            g_rp[(n * NBX + blockIdx.x) * HW + l0 + tid] = rs;
            g_vp[(n * NBX + blockIdx.x) * HW + l0 + tid] = rm;
        }
        float cs = 0.0f;
#pragma unroll
        for (int w = 0; w < 4; w++) cs += s_cs[w][tid];
        if (s0 + tid < HW)
            g_cp[(n * NBX + blockIdx.y) * HW + s0 + tid] = cs;
    }
}

// ---------------- merge: LR, vmax ----------------
__global__ __launch_bounds__(256) void rowfin_kernel() {
    const int n = blockIdx.y;
    const int l = blockIdx.x * 256 + threadIdx.x;
    if (l >= HW) return;
    float s = 0.0f, m = -CUDART_INF_F;
#pragma unroll
    for (int b = 0; b < NBX; b++) {
        s += g_rp[(n * NBX + b) * HW + l];
        m = fmaxf(m, g_vp[(n * NBX + b) * HW + l]);
    }
    g_LR[n * HW + l] = logf(s);
    g_vmax[n * HW + l] = m;
}

// ---------------- merge: LC + per-block min/max ----------------
__global__ __launch_bounds__(256) void colfin_kernel() {
    const int n = blockIdx.y;
    const int s = blockIdx.x * 256 + threadIdx.x;
    __shared__ float mn[256], mx[256];
    float lo = CUDART_INF_F, hi = -CUDART_INF_F;
    if (s < HW) {
        float acc = 0.0f;
#pragma unroll
        for (int b = 0; b < NBX; b++) acc += g_cp[(n * NBX + b) * HW + s];
        float v = logf(acc);
        g_LC[n * HW + s] = v;
        lo = v; hi = v;
    }
    const int tid = threadIdx.x;
    mn[tid] = lo; mx[tid] = hi;
    __syncthreads();
    for (int o = 128; o > 0; o >>= 1) {
        if (tid < o) {
            mn[tid] = fminf(mn[tid], mn[tid + o]);
            mx[tid] = fmaxf(mx[tid], mx[tid + o]);
        }
        __syncthreads();
    }
    if (tid == 0) {
        g_lcmin_part[n * LCPARTS + blockIdx.x] = mn[0];
        g_lcmax_part[n * LCPARTS + blockIdx.x] = mx[0];
    }
}

// ---------------- threshold from per-row score lower bounds ----------------
__global__ __launch_bounds__(256) void bound_kernel() {
    const int n = blockIdx.x;
    const int tid = threadIdx.x;
    __shared__ float s_lcmax;
    __shared__ float red1[256], red2[256];
    __shared__ int hist[2048];
    __shared__ unsigned ssum[256];
    __shared__ float s_lmn, s_lmx;

    if (tid == 0) {
        float mn = CUDART_INF_F, mx = -CUDART_INF_F;
        for (int i = 0; i < LCPARTS; i++) {
            mn = fminf(mn, g_lcmin_part[n * LCPARTS + i]);
            mx = fmaxf(mx, g_lcmax_part[n * LCPARTS + i]);
        }
        g_lcmin[n] = mn;
        s_lcmax = mx;
        g_cnt[n] = 0;
    }
    __syncthreads();
    const float lcmax = s_lcmax;

    float lmn = CUDART_INF_F, lmx = -CUDART_INF_F;
    for (int l = tid; l < HW; l += 256) {
        float L = fmaf(2.0f, g_vmax[n * HW + l], -g_LR[n * HW + l]) - lcmax;
        lmn = fminf(lmn, L); lmx = fmaxf(lmx, L);
    }
    red1[tid] = lmn; red2[tid] = lmx;
    __syncthreads();
    for (int o = 128; o > 0; o >>= 1) {
        if (tid < o) {
            red1[tid] = fminf(red1[tid], red1[tid + o]);
            red2[tid] = fmaxf(red2[tid], red2[tid + o]);
        }
        __syncthreads();
    }
    if (tid == 0) { s_lmn = red1[0]; s_lmx = red2[0]; }
    __syncthreads();
    const float Lmn = s_lmn;
    const float binw = (s_lmx - Lmn) * (1.0f / 2048.0f);
    if (binw < 1e-30f) {
        if (tid == 0) g_thrv[n] = Lmn;
        return;
    }
    for (int i = tid; i < 2048; i += 256) hist[i] = 0;
    __syncthreads();
    for (int l = tid; l < HW; l += 256) {
        float L = fmaf(2.0f, g_vmax[n * HW + l], -g_LR[n * HW + l]) - lcmax;
        int b = (int)((L - Lmn) / binw);
        b = max(0, min(2047, b));
        atomicAdd(&hist[b], 1);
    }
    __syncthreads();
    unsigned csum = 0;
#pragma unroll
    for (int i = 0; i < 8; i++) csum += (unsigned)hist[tid * 8 + i];
    ssum[tid] = csum;
    __syncthreads();
    for (int off = 1; off < 256; off <<= 1) {
        unsigned v = (tid + off < 256) ? ssum[tid + off] : 0u;
        __syncthreads();
        ssum[tid] += v;
        __syncthreads();
    }
    unsigned mine = ssum[tid];
    unsigned nxt = (tid < 255) ? ssum[tid + 1] : 0u;
    if (mine >= KTOP && nxt < KTOP) {
        unsigned cum = nxt;
        int b = tid * 8 + 7;
        for (; b > tid * 8; b--) {
            cum += (unsigned)hist[b];
            if (cum >= KTOP) break;
        }
        g_thrv[n] = Lmn + (float)(b - 1) * binw;   // one-bin safety margin
    }
}

// ---------------- collect candidates (only flagged rows) ----------------
__global__ __launch_bounds__(128) void collect_kernel() {
    const int n = blockIdx.y, l = blockIdx.x;
    const float t = g_thrv[n];
    const float LR = g_LR[n * HW + l];
    const float Bnd = fmaf(2.0f, g_vmax[n * HW + l], -LR) - g_lcmin[n];
    if (Bnd < t) return;
    const float* row = g_sm + ((size_t)(n * HW + l)) * HW;
    const float* LC = g_LC + n * HW;
    for (int s4 = threadIdx.x * 4; s4 < HW; s4 += 128 * 4) {
        float4 v = *reinterpret_cast<const float4*>(row + s4);
        float4 c = *reinterpret_cast<const float4*>(LC + s4);
        float sc[4];
        sc[0] = fmaf(2.0f, v.x, -LR) - c.x;
        sc[1] = fmaf(2.0f, v.y, -LR) - c.y;
        sc[2] = fmaf(2.0f, v.z, -LR) - c.z;
        sc[3] = fmaf(2.0f, v.w, -LR) - c.w;
#pragma unroll
        for (int q = 0; q < 4; q++) {
            if (sc[q] >= t) {
                int p = atomicAdd(&g_cnt[n], 1);
                if (p < CAP) {
                    g_cv[n * CAP + p] = sc[q];
                    g_ci[n * CAP + p] = l * HW + s4 + q;
                }
            }
        }
    }
}

// ---------------- top-100: smem bitonic sort on packed keys ----------------
__global__ __launch_bounds__(256) void select_kernel() {
    const int n = blockIdx.x;
    const int tid = threadIdx.x;
    int cnt = g_cnt[n];
    if (cnt > CAP) cnt = CAP;
    float* cv = g_cv + n * CAP;
    int* ci = g_ci + n * CAP;

    if (cnt <= 2048) {
        __shared__ unsigned long long key[2048];
        for (int i = tid; i < 2048; i += 256) {
            unsigned long long k = 0ull;
            if (i < cnt)
                k = ((unsigned long long)mono_bits(cv[i]) << 32) |
                    (unsigned long long)(0xFFFFFFFFu - (unsigned)ci[i]);
            key[i] = k;
        }
        __syncthreads();
        for (int kk = 2; kk <= 2048; kk <<= 1) {
            for (int j = kk >> 1; j > 0; j >>= 1) {
                for (int i = tid; i < 2048; i += 256) {
                    int ixj = i ^ j;
                    if (ixj > i) {
                        bool dirDesc = ((i & kk) == 0);
                        unsigned long long a = key[i], b = key[ixj];
                        if ((a < b) == dirDesc) { key[i] = b; key[ixj] = a; }
                    }
                }
                __syncthreads();
            }
        }
        if (tid < KTOP)
            g_topi[n * KTOP + tid] = (int)(0xFFFFFFFFu - (unsigned)(key[tid] & 0xFFFFFFFFull));
        return;
    }

    // fallback: iterative argmax
    __shared__ float sv[256];
    __shared__ int si[256];
    __shared__ int sp[256];
    for (int k = 0; k < KTOP; k++) {
        float bv = -CUDART_INF_F; int bi = 0x7FFFFFFF; int bp = -1;
        for (int j = tid; j < cnt; j += 256) {
            float v = cv[j]; int idx = ci[j];
            if (v > bv || (v == bv && idx < bi)) { bv = v; bi = idx; bp = j; }
        }
        sv[tid] = bv; si[tid] = bi; sp[tid] = bp;
        __syncthreads();
        for (int o = 128; o > 0; o >>= 1) {
            if (tid < o) {
                if (sv[tid + o] > sv[tid] || (sv[tid + o] == sv[tid] && si[tid + o] < si[tid])) {
                    sv[tid] = sv[tid + o]; si[tid] = si[tid + o]; sp[tid] = sp[tid + o];
                }
            }
            __syncthreads();
        }
        if (tid == 0) {
            g_topi[n * KTOP + k] = si[0];
            if (sp[0] >= 0) cv[sp[0]] = -CUDART_INF_F;
        }
        __syncthreads();
    }
}

// ---------------- embedding ----------------
__global__ __launch_bounds__(128) void prep_kernel(const float* __restrict__ W) {
    const int np = blockIdx.x;
    const int d = threadIdx.x;
    const int n = np & 3;
    const bool side1 = (np >= 4);
    float S = 0.0f, wx = 0.0f, wy = 0.0f;
    for (int k = 0; k < KTOP; k++) {
        int idx = g_topi[n * KTOP + k];
        int r = side1 ? (idx % HW) : (idx / HW);
        float cx = (float)(r % WDIM) / 60.0f;
        float cy = (float)(r / WDIM) / 60.0f;
        float w0 = W[d * (2 * KTOP) + 2 * k];
        float w1 = W[d * (2 * KTOP) + 2 * k + 1];
        S = fmaf(w0, cx, S);
        S = fmaf(w1, cy, S);
        wx += w0; wy += w1;
    }
    g_E[np * CCH + d] = -S;
    if (np == 0) { g_WX[d] = wx; g_WY[d] = wy; }
}

__global__ __launch_bounds__(256) void final_kernel(const float* __restrict__ x,
                                                    const float* __restrict__ bvec,
                                                    float* __restrict__ out) {
    const int d = blockIdx.x;
    const int np = blockIdx.y;
    const float wx = g_WX[d];
    const float wy = g_WY[d];
    const float e = g_E[np * CCH + d] + bvec[d];
    const size_t base = ((size_t)np * CCH + d) * HW;
    for (int p = threadIdx.x; p < HW; p += 256) {
        float gx = (float)(p % WDIM) / 60.0f;
        float gy = (float)(p / WDIM) / 60.0f;
        out[base + p] = x[base + p] + gx * wx + gy * wy + e;
    }
}

// ---------------- launch ----------------
extern "C" void kernel_launch(void* const* d_in, const int* in_sizes, int n_in,
                              void* d_out, int out_size) {
    (void)in_sizes; (void)n_in; (void)out_size;
    const float* x = (const float*)d_in[0];
    const float* W = (const float*)d_in[1];
    const float* b = (const float*)d_in[2];
    float* out = (float*)d_out;

    gemm_kernel<<<dim3(NBX, NBX, NBATCH), 512>>>(x);
    rowfin_kernel<<<dim3(LCPARTS, NBATCH), 256>>>();
    colfin_kernel<<<dim3(LCPARTS, NBATCH), 256>>>();
    bound_kernel<<<NBATCH, 256>>>();
    collect_kernel<<<dim3(HW, NBATCH), 128>>>();
    select_kernel<<<NBATCH, 256>>>();
    prep_kernel<<<8, 128>>>(W);
    final_kernel<<<dim3(CCH, 8), 256>>>(x, b, out);
}

// round 11
// speedup vs baseline: 3.7045x; 1.1240x over previous
#include <cuda_runtime.h>
#include <cuda_fp16.h>
#include <math_constants.h>
#include <stdint.h>

#define HW    3600
#define WDIM  60
#define CCH   128
#define NBATCH 4
#define KTOP  100
#define CAP   65536
#define NBX   29          // ceil(3600/128)
#define LCPARTS 15
#define SPH   136         // half2 row pitch (conflict-free)

// ---------------- device scratch ----------------
__device__ float g_sm[(size_t)NBATCH * HW * HW];   // 207 MB
__device__ float g_rp[NBATCH * NBX * HW];
__device__ float g_cp[NBATCH * NBX * HW];
__device__ float g_vp[NBATCH * NBX * HW];
__device__ float g_LR[NBATCH * HW];
__device__ float g_LC[NBATCH * HW];
__device__ float g_vmax[NBATCH * HW];
__device__ float g_lcmin_part[NBATCH * LCPARTS];
__device__ float g_lcmax_part[NBATCH * LCPARTS];
__device__ float g_thrv[NBATCH];
__device__ float g_lcmin[NBATCH];
__device__ int   g_cnt[NBATCH];
__device__ float g_cv[NBATCH * CAP];
__device__ int   g_ci[NBATCH * CAP];
__device__ int   g_topi[NBATCH * KTOP];
__device__ float g_E[8 * CCH];
__device__ float g_WX[CCH];
__device__ float g_WY[CCH];

// ---------------- helpers ----------------
__device__ __forceinline__ void mma_f16(float c[4], const unsigned a[4], const unsigned b[2]) {
    asm volatile(
        "mma.sync.aligned.m16n8k16.row.col.f32.f16.f16.f32 "
        "{%0,%1,%2,%3}, {%4,%5,%6,%7}, {%8,%9}, {%0,%1,%2,%3};"
        : "+f"(c[0]), "+f"(c[1]), "+f"(c[2]), "+f"(c[3])
        : "r"(a[0]), "r"(a[1]), "r"(a[2]), "r"(a[3]), "r"(b[0]), "r"(b[1]));
}
__device__ __forceinline__ unsigned mono_bits(float f) {
    unsigned b = __float_as_uint(f);
    return (b & 0x80000000u) ? ~b : (b | 0x80000000u);
}
__device__ __forceinline__ unsigned h2u(__half2 h) {
    return *reinterpret_cast<unsigned*>(&h);
}

// ---------------- GEMM (fp16 x3 split, m16n8k16, deep-pipelined loader) ----------------
// 512 threads, 16 warps in 4x4 grid, warp tile 32x32, block tile 128x128, K chunk 16.
__global__ __launch_bounds__(512, 1) void gemm_kernel(const float* __restrict__ x) {
    __shared__ __align__(16) __half2 Ah[2][8][SPH];
    __shared__ __align__(16) __half2 Al[2][8][SPH];
    __shared__ __align__(16) __half2 Bh[2][8][SPH];
    __shared__ __align__(16) __half2 Bl[2][8][SPH];
    __shared__ float s_rs[4][128];
    __shared__ float s_rm[4][128];
    __shared__ float s_cs[4][128];

    const int n  = blockIdx.z;
    const int l0 = blockIdx.y * 128;
    const int s0 = blockIdx.x * 128;
    const float* A = x + (size_t)n * CCH * HW;
    const float* B = x + (size_t)(n + NBATCH) * CCH * HW;
    const int tid = threadIdx.x;
    const int lane = tid & 31;
    const int wid = tid >> 5;
    const int g = lane >> 2, tig = lane & 3;
    const int wm = wid & 3, wn = wid >> 2;
    const int rb = wm * 32, cb = wn * 32;

    // loader role: tid<256 -> A plane, else B plane
    const int side = tid >> 8;
    const int slot = tid & 255;
    const int kp = slot >> 5;           // 0..7 (k pair within chunk)
    const int m0 = (slot & 31) << 2;    // 0..124
    const float* P = side ? B : A;
    const int base0 = side ? s0 : l0;
    const bool okc = (base0 + m0) < HW;

    float acc[2][4][4];
#pragma unroll
    for (int mi = 0; mi < 2; mi++)
#pragma unroll
        for (int ni = 0; ni < 4; ni++)
#pragma unroll
            for (int q = 0; q < 4; q++) acc[mi][ni][q] = 0.0f;

    float4 r0, r1;   // in-flight chunk held across one full iteration

    // convert + STS from (r0,r1) into stage st
    auto cvt_sts = [&](int st) {
        __half2 h0 = __floats2half2_rn(r0.x, r1.x);
        __half2 h1 = __floats2half2_rn(r0.y, r1.y);
        __half2 h2 = __floats2half2_rn(r0.z, r1.z);
        __half2 h3 = __floats2half2_rn(r0.w, r1.w);
        float2 b0 = __half22float2(h0), b1 = __half22float2(h1);
        float2 b2 = __half22float2(h2), b3 = __half22float2(h3);
        __half2 l0h = __floats2half2_rn(r0.x - b0.x, r1.x - b0.y);
        __half2 l1h = __floats2half2_rn(r0.y - b1.x, r1.y - b1.y);
        __half2 l2h = __floats2half2_rn(r0.z - b2.x, r1.z - b2.y);
        __half2 l3h = __floats2half2_rn(r0.w - b3.x, r1.w - b3.y);
        __half2* dh = side ? &Bh[st][kp][m0] : &Ah[st][kp][m0];
        __half2* dl = side ? &Bl[st][kp][m0] : &Al[st][kp][m0];
        *reinterpret_cast<uint4*>(dh) = make_uint4(h2u(h0), h2u(h1), h2u(h2), h2u(h3));
        *reinterpret_cast<uint4*>(dl) = make_uint4(h2u(l0h), h2u(l1h), h2u(l2h), h2u(l3h));
    };
    auto ldg_chunk = [&](int c) {
        const int d = c * 16 + kp * 2;
        r0 = okc ? *reinterpret_cast<const float4*>(P + (size_t)d * HW + base0 + m0)
                 : make_float4(0.f, 0.f, 0.f, 0.f);
        r1 = okc ? *reinterpret_cast<const float4*>(P + (size_t)(d + 1) * HW + base0 + m0)
                 : make_float4(0.f, 0.f, 0.f, 0.f);
    };

    // prologue: chunk0 -> stage0; chunk1 in regs
    ldg_chunk(0);
    cvt_sts(0);
    ldg_chunk(1);
    __syncthreads();

#pragma unroll
    for (int c = 0; c < 8; c++) {
        const int st = c & 1;

        // fragments from stage st (needed by mma; issue LDS first)
        unsigned ah[2][4], al[2][4], bh[4][2], bl[4][2];
#pragma unroll
        for (int mi = 0; mi < 2; mi++) {
            const int mp = rb + mi * 16 + g;
            ah[mi][0] = h2u(Ah[st][tig][mp]);
            ah[mi][1] = h2u(Ah[st][tig][mp + 8]);
            ah[mi][2] = h2u(Ah[st][tig + 4][mp]);
            ah[mi][3] = h2u(Ah[st][tig + 4][mp + 8]);
            al[mi][0] = h2u(Al[st][tig][mp]);
            al[mi][1] = h2u(Al[st][tig][mp + 8]);
            al[mi][2] = h2u(Al[st][tig + 4][mp]);
            al[mi][3] = h2u(Al[st][tig + 4][mp + 8]);
        }
#pragma unroll
        for (int ni = 0; ni < 4; ni++) {
            const int np = cb + ni * 8 + g;
            bh[ni][0] = h2u(Bh[st][tig][np]);
            bh[ni][1] = h2u(Bh[st][tig + 4][np]);
            bl[ni][0] = h2u(Bl[st][tig][np]);
            bl[ni][1] = h2u(Bl[st][tig + 4][np]);
        }

        // convert+STS chunk c+1 (regs loaded a full iteration ago) into stage st^1,
        // then issue LDG for chunk c+2. STS drains during the mma block below.
        if (c < 7) cvt_sts(st ^ 1);
        if (c < 6) ldg_chunk(c + 2);

#pragma unroll
        for (int mi = 0; mi < 2; mi++)
#pragma unroll
            for (int ni = 0; ni < 4; ni++)
                mma_f16(acc[mi][ni], ah[mi], bl[ni]);
#pragma unroll
        for (int mi = 0; mi < 2; mi++)
#pragma unroll
            for (int ni = 0; ni < 4; ni++)
                mma_f16(acc[mi][ni], al[mi], bh[ni]);
#pragma unroll
        for (int mi = 0; mi < 2; mi++)
#pragma unroll
            for (int ni = 0; ni < 4; ni++)
                mma_f16(acc[mi][ni], ah[mi], bh[ni]);

        __syncthreads();
    }

    // ---- epilogue: scale, store, exp stats ----
    const float inv = 1.0f / 12.8f;
    float rsum[2][2], rmax[2][2], csum[4][2];
#pragma unroll
    for (int i = 0; i < 2; i++)
#pragma unroll
        for (int r = 0; r < 2; r++) { rsum[i][r] = 0.0f; rmax[i][r] = -CUDART_INF_F; }
#pragma unroll
    for (int i = 0; i < 4; i++) { csum[i][0] = 0.0f; csum[i][1] = 0.0f; }

#pragma unroll
    for (int mi = 0; mi < 2; mi++) {
        const int row0 = l0 + rb + mi * 16 + g;
        const int row1 = row0 + 8;
        const bool rv0 = row0 < HW, rv1 = row1 < HW;
        float* orow0 = g_sm + ((size_t)(n * HW + row0)) * HW;
        float* orow1 = g_sm + ((size_t)(n * HW + row1)) * HW;
#pragma unroll
        for (int ni = 0; ni < 4; ni++) {
            const int sc0 = s0 + cb + ni * 8 + tig * 2;
            const bool cv0 = sc0 < HW, cv1 = (sc0 + 1) < HW;
            float v0 = acc[mi][ni][0] * inv;
            float v1 = acc[mi][ni][1] * inv;
            float v2 = acc[mi][ni][2] * inv;
            float v3 = acc[mi][ni][3] * inv;
            if (rv0 && cv0) *reinterpret_cast<float2*>(orow0 + sc0) = make_float2(v0, v1);
            if (rv1 && cv0) *reinterpret_cast<float2*>(orow1 + sc0) = make_float2(v2, v3);
            float e0 = cv0 ? __expf(v0) : 0.0f;
            float e1 = cv1 ? __expf(v1) : 0.0f;
            float e2 = cv0 ? __expf(v2) : 0.0f;
            float e3 = cv1 ? __expf(v3) : 0.0f;
            rsum[mi][0] += e0 + e1;
            rsum[mi][1] += e2 + e3;
            rmax[mi][0] = fmaxf(rmax[mi][0], fmaxf(cv0 ? v0 : -CUDART_INF_F, cv1 ? v1 : -CUDART_INF_F));
            rmax[mi][1] = fmaxf(rmax[mi][1], fmaxf(cv0 ? v2 : -CUDART_INF_F, cv1 ? v3 : -CUDART_INF_F));
            csum[ni][0] += (rv0 ? e0 : 0.0f) + (rv1 ? e2 : 0.0f);
            csum[ni][1] += (rv0 ? e1 : 0.0f) + (rv1 ? e3 : 0.0f);
        }
    }

#pragma unroll
    for (int m = 1; m < 4; m <<= 1) {
#pragma unroll
        for (int mi = 0; mi < 2; mi++)
#pragma unroll
            for (int r = 0; r < 2; r++) {
                rsum[mi][r] += __shfl_xor_sync(0xffffffffu, rsum[mi][r], m);
                rmax[mi][r] = fmaxf(rmax[mi][r], __shfl_xor_sync(0xffffffffu, rmax[mi][r], m));
            }
    }
    if (tig == 0) {
#pragma unroll
        for (int mi = 0; mi < 2; mi++) {
            const int rr = rb + mi * 16 + g;
            s_rs[wn][rr] = rsum[mi][0];
            s_rs[wn][rr + 8] = rsum[mi][1];
            s_rm[wn][rr] = rmax[mi][0];
            s_rm[wn][rr + 8] = rmax[mi][1];
        }
    }
#pragma unroll
    for (int m = 4; m < 32; m <<= 1) {
#pragma unroll
        for (int ni = 0; ni < 4; ni++)
#pragma unroll
            for (int q = 0; q < 2; q++)
                csum[ni][q] += __shfl_xor_sync(0xffffffffu, csum[ni][q], m);
    }
    if (g == 0) {
#pragma unroll
        for (int ni = 0; ni < 4; ni++) {
            s_cs[wm][cb + ni * 8 + tig * 2]     = csum[ni][0];
            s_cs[wm][cb + ni * 8 + tig * 2 + 1] = csum[ni][1];
        }
    }
    __syncthreads();
    if (tid < 128) {
        float rs = 0.0f, rm = -CUDART_INF_F;
#pragma unroll
        for (int w = 0; w < 4; w++) { rs += s_rs[w][tid]; rm = fmaxf(rm, s_rm[w][tid]); }
        if (l0 + tid < HW) {
            g_rp[(n * NBX + blockIdx.x) * HW + l0 + tid] = rs;
            g_vp[(n * NBX + blockIdx.x) * HW + l0 + tid] = rm;
        }
        float cs = 0.0f;
#pragma unroll
        for (int w = 0; w < 4; w++) cs += s_cs[w][tid];
        if (s0 + tid < HW)
            g_cp[(n * NBX + blockIdx.y) * HW + s0 + tid] = cs;
    }
}

// ---------------- merge: LR, vmax ----------------
__global__ __launch_bounds__(256) void rowfin_kernel() {
    const int n = blockIdx.y;
    const int l = blockIdx.x * 256 + threadIdx.x;
    if (l >= HW) return;
    float s = 0.0f, m = -CUDART_INF_F;
#pragma unroll
    for (int b = 0; b < NBX; b++) {
        s += g_rp[(n * NBX + b) * HW + l];
        m = fmaxf(m, g_vp[(n * NBX + b) * HW + l]);
    }
    g_LR[n * HW + l] = logf(s);
    g_vmax[n * HW + l] = m;
}

// ---------------- merge: LC + per-block min/max ----------------
__global__ __launch_bounds__(256) void colfin_kernel() {
    const int n = blockIdx.y;
    const int s = blockIdx.x * 256 + threadIdx.x;
    __shared__ float mn[256], mx[256];
    float lo = CUDART_INF_F, hi = -CUDART_INF_F;
    if (s < HW) {
        float acc = 0.0f;
#pragma unroll
        for (int b = 0; b < NBX; b++) acc += g_cp[(n * NBX + b) * HW + s];
        float v = logf(acc);
        g_LC[n * HW + s] = v;
        lo = v; hi = v;
    }
    const int tid = threadIdx.x;
    mn[tid] = lo; mx[tid] = hi;
    __syncthreads();
    for (int o = 128; o > 0; o >>= 1) {
        if (tid < o) {
            mn[tid] = fminf(mn[tid], mn[tid + o]);
            mx[tid] = fmaxf(mx[tid], mx[tid + o]);
        }
        __syncthreads();
    }
    if (tid == 0) {
        g_lcmin_part[n * LCPARTS + blockIdx.x] = mn[0];
        g_lcmax_part[n * LCPARTS + blockIdx.x] = mx[0];
    }
}

// ---------------- threshold from per-row score lower bounds ----------------
__global__ __launch_bounds__(256) void bound_kernel() {
    const int n = blockIdx.x;
    const int tid = threadIdx.x;
    __shared__ float s_lcmax;
    __shared__ float red1[256], red2[256];
    __shared__ int hist[2048];
    __shared__ unsigned ssum[256];
    __shared__ float s_lmn, s_lmx;

    if (tid == 0) {
        float mn = CUDART_INF_F, mx = -CUDART_INF_F;
        for (int i = 0; i < LCPARTS; i++) {
            mn = fminf(mn, g_lcmin_part[n * LCPARTS + i]);
            mx = fmaxf(mx, g_lcmax_part[n * LCPARTS + i]);
        }
        g_lcmin[n] = mn;
        s_lcmax = mx;
        g_cnt[n] = 0;
    }
    __syncthreads();
    const float lcmax = s_lcmax;

    float lmn = CUDART_INF_F, lmx = -CUDART_INF_F;
    for (int l = tid; l < HW; l += 256) {
        float L = fmaf(2.0f, g_vmax[n * HW + l], -g_LR[n * HW + l]) - lcmax;
        lmn = fminf(lmn, L); lmx = fmaxf(lmx, L);
    }
    red1[tid] = lmn; red2[tid] = lmx;
    __syncthreads();
    for (int o = 128; o > 0; o >>= 1) {
        if (tid < o) {
            red1[tid] = fminf(red1[tid], red1[tid + o]);
            red2[tid] = fmaxf(red2[tid], red2[tid + o]);
        }
        __syncthreads();
    }
    if (tid == 0) { s_lmn = red1[0]; s_lmx = red2[0]; }
    __syncthreads();
    const float Lmn = s_lmn;
    const float binw = (s_lmx - Lmn) * (1.0f / 2048.0f);
    if (binw < 1e-30f) {
        if (tid == 0) g_thrv[n] = Lmn;
        return;
    }
    for (int i = tid; i < 2048; i += 256) hist[i] = 0;
    __syncthreads();
    for (int l = tid; l < HW; l += 256) {
        float L = fmaf(2.0f, g_vmax[n * HW + l], -g_LR[n * HW + l]) - lcmax;
        int b = (int)((L - Lmn) / binw);
        b = max(0, min(2047, b));
        atomicAdd(&hist[b], 1);
    }
    __syncthreads();
    unsigned csum = 0;
#pragma unroll
    for (int i = 0; i < 8; i++) csum += (unsigned)hist[tid * 8 + i];
    ssum[tid] = csum;
    __syncthreads();
    for (int off = 1; off < 256; off <<= 1) {
        unsigned v = (tid + off < 256) ? ssum[tid + off] : 0u;
        __syncthreads();
        ssum[tid] += v;
        __syncthreads();
    }
    unsigned mine = ssum[tid];
    unsigned nxt = (tid < 255) ? ssum[tid + 1] : 0u;
    if (mine >= KTOP && nxt < KTOP) {
        unsigned cum = nxt;
        int b = tid * 8 + 7;
        for (; b > tid * 8; b--) {
            cum += (unsigned)hist[b];
            if (cum >= KTOP) break;
        }
        g_thrv[n] = Lmn + (float)(b - 1) * binw;   // one-bin safety margin
    }
}

// ---------------- collect candidates (only flagged rows) ----------------
__global__ __launch_bounds__(128) void collect_kernel() {
    const int n = blockIdx.y, l = blockIdx.x;
    const float t = g_thrv[n];
    const float LR = g_LR[n * HW + l];
    const float Bnd = fmaf(2.0f, g_vmax[n * HW + l], -LR) - g_lcmin[n];
    if (Bnd < t) return;
    const float* row = g_sm + ((size_t)(n * HW + l)) * HW;
    const float* LC = g_LC + n * HW;
    for (int s4 = threadIdx.x * 4; s4 < HW; s4 += 128 * 4) {
        float4 v = *reinterpret_cast<const float4*>(row + s4);
        float4 c = *reinterpret_cast<const float4*>(LC + s4);
        float sc[4];
        sc[0] = fmaf(2.0f, v.x, -LR) - c.x;
        sc[1] = fmaf(2.0f, v.y, -LR) - c.y;
        sc[2] = fmaf(2.0f, v.z, -LR) - c.z;
        sc[3] = fmaf(2.0f, v.w, -LR) - c.w;
#pragma unroll
        for (int q = 0; q < 4; q++) {
            if (sc[q] >= t) {
                int p = atomicAdd(&g_cnt[n], 1);
                if (p < CAP) {
                    g_cv[n * CAP + p] = sc[q];
                    g_ci[n * CAP + p] = l * HW + s4 + q;
                }
            }
        }
    }
}

// ---------------- top-100: smem bitonic sort on packed keys ----------------
__global__ __launch_bounds__(256) void select_kernel() {
    const int n = blockIdx.x;
    const int tid = threadIdx.x;
    int cnt = g_cnt[n];
    if (cnt > CAP) cnt = CAP;
    float* cv = g_cv + n * CAP;
    int* ci = g_ci + n * CAP;

    if (cnt <= 2048) {
        __shared__ unsigned long long key[2048];
        for (int i = tid; i < 2048; i += 256) {
            unsigned long long k = 0ull;
            if (i < cnt)
                k = ((unsigned long long)mono_bits(cv[i]) << 32) |
                    (unsigned long long)(0xFFFFFFFFu - (unsigned)ci[i]);
            key[i] = k;
        }
        __syncthreads();
        for (int kk = 2; kk <= 2048; kk <<= 1) {
            for (int j = kk >> 1; j > 0; j >>= 1) {
                for (int i = tid; i < 2048; i += 256) {
                    int ixj = i ^ j;
                    if (ixj > i) {
                        bool dirDesc = ((i & kk) == 0);
                        unsigned long long a = key[i], b = key[ixj];
                        if ((a < b) == dirDesc) { key[i] = b; key[ixj] = a; }
                    }
                }
                __syncthreads();
            }
        }
        if (tid < KTOP)
            g_topi[n * KTOP + tid] = (int)(0xFFFFFFFFu - (unsigned)(key[tid] & 0xFFFFFFFFull));
        return;
    }

    // fallback: iterative argmax
    __shared__ float sv[256];
    __shared__ int si[256];
    __shared__ int sp[256];
    for (int k = 0; k < KTOP; k++) {
        float bv = -CUDART_INF_F; int bi = 0x7FFFFFFF; int bp = -1;
        for (int j = tid; j < cnt; j += 256) {
            float v = cv[j]; int idx = ci[j];
            if (v > bv || (v == bv && idx < bi)) { bv = v; bi = idx; bp = j; }
        }
        sv[tid] = bv; si[tid] = bi; sp[tid] = bp;
        __syncthreads();
        for (int o = 128; o > 0; o >>= 1) {
            if (tid < o) {
                if (sv[tid + o] > sv[tid] || (sv[tid + o] == sv[tid] && si[tid + o] < si[tid])) {
                    sv[tid] = sv[tid + o]; si[tid] = si[tid + o]; sp[tid] = sp[tid + o];
                }
            }
            __syncthreads();
        }
        if (tid == 0) {
            g_topi[n * KTOP + k] = si[0];
            if (sp[0] >= 0) cv[sp[0]] = -CUDART_INF_F;
        }
        __syncthreads();
    }
}

// ---------------- embedding ----------------
__global__ __launch_bounds__(128) void prep_kernel(const float* __restrict__ W) {
    const int np = blockIdx.x;
    const int d = threadIdx.x;
    const int n = np & 3;
    const bool side1 = (np >= 4);
    float S = 0.0f, wx = 0.0f, wy = 0.0f;
    for (int k = 0; k < KTOP; k++) {
        int idx = g_topi[n * KTOP + k];
        int r = side1 ? (idx % HW) : (idx / HW);
        float cx = (float)(r % WDIM) / 60.0f;
        float cy = (float)(r / WDIM) / 60.0f;
        float w0 = W[d * (2 * KTOP) + 2 * k];
        float w1 = W[d * (2 * KTOP) + 2 * k + 1];
        S = fmaf(w0, cx, S);
        S = fmaf(w1, cy, S);
        wx += w0; wy += w1;
    }
    g_E[np * CCH + d] = -S;
    if (np == 0) { g_WX[d] = wx; g_WY[d] = wy; }
}

__global__ __launch_bounds__(256) void final_kernel(const float* __restrict__ x,
                                                    const float* __restrict__ bvec,
                                                    float* __restrict__ out) {
    const int d = blockIdx.x;
    const int np = blockIdx.y;
    const float wx = g_WX[d];
    const float wy = g_WY[d];
    const float e = g_E[np * CCH + d] + bvec[d];
    const size_t base = ((size_t)np * CCH + d) * HW;
    for (int p = threadIdx.x; p < HW; p += 256) {
        float gx = (float)(p % WDIM) / 60.0f;
        float gy = (float)(p / WDIM) / 60.0f;
        out[base + p] = x[base + p] + gx * wx + gy * wy + e;
    }
}

// ---------------- launch ----------------
extern "C" void kernel_launch(void* const* d_in, const int* in_sizes, int n_in,
                              void* d_out, int out_size) {
    (void)in_sizes; (void)n_in; (void)out_size;
    const float* x = (const float*)d_in[0];
    const float* W = (const float*)d_in[1];
    const float* b = (const float*)d_in[2];
    float* out = (float*)d_out;

    gemm_kernel<<<dim3(NBX, NBX, NBATCH), 512>>>(x);
    rowfin_kernel<<<dim3(LCPARTS, NBATCH), 256>>>();
    colfin_kernel<<<dim3(LCPARTS, NBATCH), 256>>>();
    bound_kernel<<<NBATCH, 256>>>();
    collect_kernel<<<dim3(HW, NBATCH), 128>>>();
    select_kernel<<<NBATCH, 256>>>();
    prep_kernel<<<8, 128>>>(W);
    final_kernel<<<dim3(CCH, 8), 256>>>(x, b, out);
}

// round 12
// speedup vs baseline: 3.7600x; 1.0150x over previous
#include <cuda_runtime.h>
#include <cuda_fp16.h>
#include <math_constants.h>
#include <stdint.h>

#define HW    3600
#define WDIM  60
#define CCH   128
#define NBATCH 4
#define KTOP  100
#define CAP   65536
#define NBX   29          // ceil(3600/128)
#define LCPARTS 15
#define SPH   136         // half2 row pitch (conflict-free)

// ---------------- device scratch ----------------
__device__ float g_sm[(size_t)NBATCH * HW * HW];   // 207 MB
__device__ float g_rp[NBATCH * NBX * HW];
__device__ float g_cp[NBATCH * NBX * HW];
__device__ float g_vp[NBATCH * NBX * HW];
__device__ float g_LR[NBATCH * HW];
__device__ float g_LC[NBATCH * HW];
__device__ float g_vmax[NBATCH * HW];
__device__ float g_rowbound[NBATCH * HW];
__device__ float g_lcmin_blk[NBATCH * NBX];
__device__ float g_lcmax_part[NBATCH * LCPARTS];
__device__ float g_thrv[NBATCH];
__device__ int   g_cnt[NBATCH];
__device__ float g_cv[NBATCH * CAP];
__device__ int   g_ci[NBATCH * CAP];
__device__ int   g_topi[NBATCH * KTOP];
__device__ float g_E[8 * CCH];
__device__ float g_WX[CCH];
__device__ float g_WY[CCH];

// ---------------- helpers ----------------
__device__ __forceinline__ void mma_f16(float c[4], const unsigned a[4], const unsigned b[2]) {
    asm volatile(
        "mma.sync.aligned.m16n8k16.row.col.f32.f16.f16.f32 "
        "{%0,%1,%2,%3}, {%4,%5,%6,%7}, {%8,%9}, {%0,%1,%2,%3};"
        : "+f"(c[0]), "+f"(c[1]), "+f"(c[2]), "+f"(c[3])
        : "r"(a[0]), "r"(a[1]), "r"(a[2]), "r"(a[3]), "r"(b[0]), "r"(b[1]));
}
__device__ __forceinline__ unsigned mono_bits(float f) {
    unsigned b = __float_as_uint(f);
    return (b & 0x80000000u) ? ~b : (b | 0x80000000u);
}
__device__ __forceinline__ unsigned h2u(__half2 h) {
    return *reinterpret_cast<unsigned*>(&h);
}

// ---------------- GEMM (fp16 x3 split, m16n8k16, deep-pipelined loader) ----------------
__global__ __launch_bounds__(512, 1) void gemm_kernel(const float* __restrict__ x) {
    __shared__ __align__(16) __half2 Ah[2][8][SPH];
    __shared__ __align__(16) __half2 Al[2][8][SPH];
    __shared__ __align__(16) __half2 Bh[2][8][SPH];
    __shared__ __align__(16) __half2 Bl[2][8][SPH];
    __shared__ float s_rs[4][128];
    __shared__ float s_rm[4][128];
    __shared__ float s_cs[4][128];

    const int n  = blockIdx.z;
    const int l0 = blockIdx.y * 128;
    const int s0 = blockIdx.x * 128;
    const float* A = x + (size_t)n * CCH * HW;
    const float* B = x + (size_t)(n + NBATCH) * CCH * HW;
    const int tid = threadIdx.x;
    const int lane = tid & 31;
    const int wid = tid >> 5;
    const int g = lane >> 2, tig = lane & 3;
    const int wm = wid & 3, wn = wid >> 2;
    const int rb = wm * 32, cb = wn * 32;

    const int side = tid >> 8;
    const int slot = tid & 255;
    const int kp = slot >> 5;
    const int m0 = (slot & 31) << 2;
    const float* P = side ? B : A;
    const int base0 = side ? s0 : l0;
    const bool okc = (base0 + m0) < HW;

    float acc[2][4][4];
#pragma unroll
    for (int mi = 0; mi < 2; mi++)
#pragma unroll
        for (int ni = 0; ni < 4; ni++)
#pragma unroll
            for (int q = 0; q < 4; q++) acc[mi][ni][q] = 0.0f;

    float4 r0, r1;

    auto cvt_sts = [&](int st) {
        __half2 h0 = __floats2half2_rn(r0.x, r1.x);
        __half2 h1 = __floats2half2_rn(r0.y, r1.y);
        __half2 h2 = __floats2half2_rn(r0.z, r1.z);
        __half2 h3 = __floats2half2_rn(r0.w, r1.w);
        float2 b0 = __half22float2(h0), b1 = __half22float2(h1);
        float2 b2 = __half22float2(h2), b3 = __half22float2(h3);
        __half2 l0h = __floats2half2_rn(r0.x - b0.x, r1.x - b0.y);
        __half2 l1h = __floats2half2_rn(r0.y - b1.x, r1.y - b1.y);
        __half2 l2h = __floats2half2_rn(r0.z - b2.x, r1.z - b2.y);
        __half2 l3h = __floats2half2_rn(r0.w - b3.x, r1.w - b3.y);
        __half2* dh = side ? &Bh[st][kp][m0] : &Ah[st][kp][m0];
        __half2* dl = side ? &Bl[st][kp][m0] : &Al[st][kp][m0];
        *reinterpret_cast<uint4*>(dh) = make_uint4(h2u(h0), h2u(h1), h2u(h2), h2u(h3));
        *reinterpret_cast<uint4*>(dl) = make_uint4(h2u(l0h), h2u(l1h), h2u(l2h), h2u(l3h));
    };
    auto ldg_chunk = [&](int c) {
        const int d = c * 16 + kp * 2;
        r0 = okc ? *reinterpret_cast<const float4*>(P + (size_t)d * HW + base0 + m0)
                 : make_float4(0.f, 0.f, 0.f, 0.f);
        r1 = okc ? *reinterpret_cast<const float4*>(P + (size_t)(d + 1) * HW + base0 + m0)
                 : make_float4(0.f, 0.f, 0.f, 0.f);
    };

    ldg_chunk(0);
    cvt_sts(0);
    ldg_chunk(1);
    __syncthreads();

#pragma unroll
    for (int c = 0; c < 8; c++) {
        const int st = c & 1;
        unsigned ah[2][4], al[2][4], bh[4][2], bl[4][2];
#pragma unroll
        for (int mi = 0; mi < 2; mi++) {
            const int mp = rb + mi * 16 + g;
            ah[mi][0] = h2u(Ah[st][tig][mp]);
            ah[mi][1] = h2u(Ah[st][tig][mp + 8]);
            ah[mi][2] = h2u(Ah[st][tig + 4][mp]);
            ah[mi][3] = h2u(Ah[st][tig + 4][mp + 8]);
            al[mi][0] = h2u(Al[st][tig][mp]);
            al[mi][1] = h2u(Al[st][tig][mp + 8]);
            al[mi][2] = h2u(Al[st][tig + 4][mp]);
            al[mi][3] = h2u(Al[st][tig + 4][mp + 8]);
        }
#pragma unroll
        for (int ni = 0; ni < 4; ni++) {
            const int np = cb + ni * 8 + g;
            bh[ni][0] = h2u(Bh[st][tig][np]);
            bh[ni][1] = h2u(Bh[st][tig + 4][np]);
            bl[ni][0] = h2u(Bl[st][tig][np]);
            bl[ni][1] = h2u(Bl[st][tig + 4][np]);
        }
        if (c < 7) cvt_sts(st ^ 1);
        if (c < 6) ldg_chunk(c + 2);

#pragma unroll
        for (int mi = 0; mi < 2; mi++)
#pragma unroll
            for (int ni = 0; ni < 4; ni++)
                mma_f16(acc[mi][ni], ah[mi], bl[ni]);
#pragma unroll
        for (int mi = 0; mi < 2; mi++)
#pragma unroll
            for (int ni = 0; ni < 4; ni++)
                mma_f16(acc[mi][ni], al[mi], bh[ni]);
#pragma unroll
        for (int mi = 0; mi < 2; mi++)
#pragma unroll
            for (int ni = 0; ni < 4; ni++)
                mma_f16(acc[mi][ni], ah[mi], bh[ni]);

        __syncthreads();
    }

    // ---- epilogue: scale, store, exp stats ----
    const float inv = 1.0f / 12.8f;
    float rsum[2][2], rmax[2][2], csum[4][2];
#pragma unroll
    for (int i = 0; i < 2; i++)
#pragma unroll
        for (int r = 0; r < 2; r++) { rsum[i][r] = 0.0f; rmax[i][r] = -CUDART_INF_F; }
#pragma unroll
    for (int i = 0; i < 4; i++) { csum[i][0] = 0.0f; csum[i][1] = 0.0f; }

#pragma unroll
    for (int mi = 0; mi < 2; mi++) {
        const int row0 = l0 + rb + mi * 16 + g;
        const int row1 = row0 + 8;
        const bool rv0 = row0 < HW, rv1 = row1 < HW;
        float* orow0 = g_sm + ((size_t)(n * HW + row0)) * HW;
        float* orow1 = g_sm + ((size_t)(n * HW + row1)) * HW;
#pragma unroll
        for (int ni = 0; ni < 4; ni++) {
            const int sc0 = s0 + cb + ni * 8 + tig * 2;
            const bool cv0 = sc0 < HW, cv1 = (sc0 + 1) < HW;
            float v0 = acc[mi][ni][0] * inv;
            float v1 = acc[mi][ni][1] * inv;
            float v2 = acc[mi][ni][2] * inv;
            float v3 = acc[mi][ni][3] * inv;
            if (rv0 && cv0) *reinterpret_cast<float2*>(orow0 + sc0) = make_float2(v0, v1);
            if (rv1 && cv0) *reinterpret_cast<float2*>(orow1 + sc0) = make_float2(v2, v3);
            float e0 = cv0 ? __expf(v0) : 0.0f;
            float e1 = cv1 ? __expf(v1) : 0.0f;
            float e2 = cv0 ? __expf(v2) : 0.0f;
            float e3 = cv1 ? __expf(v3) : 0.0f;
            rsum[mi][0] += e0 + e1;
            rsum[mi][1] += e2 + e3;
            rmax[mi][0] = fmaxf(rmax[mi][0], fmaxf(cv0 ? v0 : -CUDART_INF_F, cv1 ? v1 : -CUDART_INF_F));
            rmax[mi][1] = fmaxf(rmax[mi][1], fmaxf(cv0 ? v2 : -CUDART_INF_F, cv1 ? v3 : -CUDART_INF_F));
            csum[ni][0] += (rv0 ? e0 : 0.0f) + (rv1 ? e2 : 0.0f);
            csum[ni][1] += (rv0 ? e1 : 0.0f) + (rv1 ? e3 : 0.0f);
        }
    }

#pragma unroll
    for (int m = 1; m < 4; m <<= 1) {
#pragma unroll
        for (int mi = 0; mi < 2; mi++)
#pragma unroll
            for (int r = 0; r < 2; r++) {
                rsum[mi][r] += __shfl_xor_sync(0xffffffffu, rsum[mi][r], m);
                rmax[mi][r] = fmaxf(rmax[mi][r], __shfl_xor_sync(0xffffffffu, rmax[mi][r], m));
            }
    }
    if (tig == 0) {
#pragma unroll
        for (int mi = 0; mi < 2; mi++) {
            const int rr = rb + mi * 16 + g;
            s_rs[wn][rr] = rsum[mi][0];
            s_rs[wn][rr + 8] = rsum[mi][1];
            s_rm[wn][rr] = rmax[mi][0];
            s_rm[wn][rr + 8] = rmax[mi][1];
        }
    }
#pragma unroll
    for (int m = 4; m < 32; m <<= 1) {
#pragma unroll
        for (int ni = 0; ni < 4; ni++)
#pragma unroll
            for (int q = 0; q < 2; q++)
                csum[ni][q] += __shfl_xor_sync(0xffffffffu, csum[ni][q], m);
    }
    if (g == 0) {
#pragma unroll
        for (int ni = 0; ni < 4; ni++) {
            s_cs[wm][cb + ni * 8 + tig * 2]     = csum[ni][0];
            s_cs[wm][cb + ni * 8 + tig * 2 + 1] = csum[ni][1];
        }
    }
    __syncthreads();
    if (tid < 128) {
        float rs = 0.0f, rm = -CUDART_INF_F;
#pragma unroll
        for (int w = 0; w < 4; w++) { rs += s_rs[w][tid]; rm = fmaxf(rm, s_rm[w][tid]); }
        if (l0 + tid < HW) {
            g_rp[(n * NBX + blockIdx.x) * HW + l0 + tid] = rs;
            g_vp[(n * NBX + blockIdx.x) * HW + l0 + tid] = rm;
        }
        float cs = 0.0f;
#pragma unroll
        for (int w = 0; w < 4; w++) cs += s_cs[w][tid];
        if (s0 + tid < HW)
            g_cp[(n * NBX + blockIdx.y) * HW + s0 + tid] = cs;
    }
}

// ---------------- colfin: LC, per-128-block LC min, lcmax partials ----------------
__global__ __launch_bounds__(256) void colfin_kernel() {
    const int n = blockIdx.y;
    const int s = blockIdx.x * 256 + threadIdx.x;
    __shared__ float mn[256], mx[256];
    float v = CUDART_INF_F;
    float hi = -CUDART_INF_F;
    if (s < HW) {
        float acc = 0.0f;
#pragma unroll
        for (int b = 0; b < NBX; b++) acc += g_cp[(n * NBX + b) * HW + s];
        v = logf(acc);
        g_LC[n * HW + s] = v;
        hi = v;
    }
    const int tid = threadIdx.x;
    mn[tid] = v; mx[tid] = hi;
    __syncthreads();
    // per-128-half min (two blocks per CTA)
    for (int o = 64; o > 0; o >>= 1) {
        if ((tid & 127) < o) mn[tid] = fminf(mn[tid], mn[tid + o]);
        __syncthreads();
    }
    if ((tid & 127) == 0) {
        int blk = (blockIdx.x * 256 + tid) >> 7;
        if (blk < NBX) g_lcmin_blk[n * NBX + blk] = mn[tid];
    }
    // global lcmax partial
    for (int o = 128; o > 0; o >>= 1) {
        if (tid < o) mx[tid] = fmaxf(mx[tid], mx[tid + o]);
        __syncthreads();
    }
    if (tid == 0) g_lcmax_part[n * LCPARTS + blockIdx.x] = mx[0];
}

// ---------------- rowfin: LR, vmax, per-row score upper bound ----------------
__global__ __launch_bounds__(256) void rowfin_kernel() {
    const int n = blockIdx.y;
    const int l = blockIdx.x * 256 + threadIdx.x;
    __shared__ float lcb[NBX];
    if (threadIdx.x < NBX) lcb[threadIdx.x] = g_lcmin_blk[n * NBX + threadIdx.x];
    __syncthreads();
    if (l >= HW) return;
    float s = 0.0f, m = -CUDART_INF_F, rbnd = -CUDART_INF_F;
#pragma unroll
    for (int b = 0; b < NBX; b++) {
        float vp = g_vp[(n * NBX + b) * HW + l];
        s += g_rp[(n * NBX + b) * HW + l];
        m = fmaxf(m, vp);
        rbnd = fmaxf(rbnd, fmaf(2.0f, vp, -lcb[b]));
    }
    float LR = logf(s);
    g_LR[n * HW + l] = LR;
    g_vmax[n * HW + l] = m;
    g_rowbound[n * HW + l] = rbnd - LR;
}

// ---------------- threshold from per-row score lower bounds ----------------
__global__ __launch_bounds__(256) void bound_kernel() {
    const int n = blockIdx.x;
    const int tid = threadIdx.x;
    __shared__ float s_lcmax;
    __shared__ float red1[256], red2[256];
    __shared__ int hist[2048];
    __shared__ unsigned ssum[256];
    __shared__ float s_lmn, s_lmx;

    if (tid == 0) {
        float mx = -CUDART_INF_F;
        for (int i = 0; i < LCPARTS; i++) mx = fmaxf(mx, g_lcmax_part[n * LCPARTS + i]);
        s_lcmax = mx;
        g_cnt[n] = 0;
    }
    __syncthreads();
    const float lcmax = s_lcmax;

    float lmn = CUDART_INF_F, lmx = -CUDART_INF_F;
    for (int l = tid; l < HW; l += 256) {
        float L = fmaf(2.0f, g_vmax[n * HW + l], -g_LR[n * HW + l]) - lcmax;
        lmn = fminf(lmn, L); lmx = fmaxf(lmx, L);
    }
    red1[tid] = lmn; red2[tid] = lmx;
    __syncthreads();
    for (int o = 128; o > 0; o >>= 1) {
        if (tid < o) {
            red1[tid] = fminf(red1[tid], red1[tid + o]);
            red2[tid] = fmaxf(red2[tid], red2[tid + o]);
        }
        __syncthreads();
    }
    if (tid == 0) { s_lmn = red1[0]; s_lmx = red2[0]; }
    __syncthreads();
    const float Lmn = s_lmn;
    const float binw = (s_lmx - Lmn) * (1.0f / 2048.0f);
    if (binw < 1e-30f) {
        if (tid == 0) g_thrv[n] = Lmn;
        return;
    }
    for (int i = tid; i < 2048; i += 256) hist[i] = 0;
    __syncthreads();
    for (int l = tid; l < HW; l += 256) {
        float L = fmaf(2.0f, g_vmax[n * HW + l], -g_LR[n * HW + l]) - lcmax;
        int b = (int)((L - Lmn) / binw);
        b = max(0, min(2047, b));
        atomicAdd(&hist[b], 1);
    }
    __syncthreads();
    unsigned csum = 0;
#pragma unroll
    for (int i = 0; i < 8; i++) csum += (unsigned)hist[tid * 8 + i];
    ssum[tid] = csum;
    __syncthreads();
    for (int off = 1; off < 256; off <<= 1) {
        unsigned v = (tid + off < 256) ? ssum[tid + off] : 0u;
        __syncthreads();
        ssum[tid] += v;
        __syncthreads();
    }
    unsigned mine = ssum[tid];
    unsigned nxt = (tid < 255) ? ssum[tid + 1] : 0u;
    if (mine >= KTOP && nxt < KTOP) {
        unsigned cum = nxt;
        int b = tid * 8 + 7;
        for (; b > tid * 8; b--) {
            cum += (unsigned)hist[b];
            if (cum >= KTOP) break;
        }
        g_thrv[n] = Lmn + (float)(b - 1) * binw;   // one-bin safety margin
    }
}

// ---------------- collect: block-pruned candidate scan ----------------
__global__ __launch_bounds__(128) void collect_kernel() {
    const int n = blockIdx.y, l = blockIdx.x;
    const float t = g_thrv[n];
    if (g_rowbound[n * HW + l] < t) return;
    const float LR = g_LR[n * HW + l];
    __shared__ unsigned s_mask;
    const int tid = threadIdx.x;
    if (tid < 32) {
        bool flag = false;
        if (tid < NBX) {
            float vp = g_vp[(n * NBX + tid) * HW + l];
            flag = (fmaf(2.0f, vp, -LR) - g_lcmin_blk[n * NBX + tid]) >= t;
        }
        unsigned m = __ballot_sync(0xffffffffu, flag);
        if (tid == 0) s_mask = m;
    }
    __syncthreads();
    unsigned mask = s_mask;
    const float* row = g_sm + ((size_t)(n * HW + l)) * HW;
    const float* LC = g_LC + n * HW;
    while (mask) {
        int b = __ffs(mask) - 1;
        mask &= mask - 1;
        int s = b * 128 + tid;
        if (s < HW) {
            float sc = fmaf(2.0f, row[s], -LR) - LC[s];
            if (sc >= t) {
                int p = atomicAdd(&g_cnt[n], 1);
                if (p < CAP) {
                    g_cv[n * CAP + p] = sc;
                    g_ci[n * CAP + p] = l * HW + s;
                }
            }
        }
    }
}

// ---------------- top-100: smem bitonic sort on packed keys ----------------
__global__ __launch_bounds__(256) void select_kernel() {
    const int n = blockIdx.x;
    const int tid = threadIdx.x;
    int cnt = g_cnt[n];
    if (cnt > CAP) cnt = CAP;
    float* cv = g_cv + n * CAP;
    int* ci = g_ci + n * CAP;

    if (cnt <= 2048) {
        __shared__ unsigned long long key[2048];
        for (int i = tid; i < 2048; i += 256) {
            unsigned long long k = 0ull;
            if (i < cnt)
                k = ((unsigned long long)mono_bits(cv[i]) << 32) |
                    (unsigned long long)(0xFFFFFFFFu - (unsigned)ci[i]);
            key[i] = k;
        }
        __syncthreads();
        for (int kk = 2; kk <= 2048; kk <<= 1) {
            for (int j = kk >> 1; j > 0; j >>= 1) {
                for (int i = tid; i < 2048; i += 256) {
                    int ixj = i ^ j;
                    if (ixj > i) {
                        bool dirDesc = ((i & kk) == 0);
                        unsigned long long a = key[i], b = key[ixj];
                        if ((a < b) == dirDesc) { key[i] = b; key[ixj] = a; }
                    }
                }
                __syncthreads();
            }
        }
        if (tid < KTOP)
            g_topi[n * KTOP + tid] = (int)(0xFFFFFFFFu - (unsigned)(key[tid] & 0xFFFFFFFFull));
        return;
    }

    // fallback: iterative argmax
    __shared__ float sv[256];
    __shared__ int si[256];
    __shared__ int sp[256];
    for (int k = 0; k < KTOP; k++) {
        float bv = -CUDART_INF_F; int bi = 0x7FFFFFFF; int bp = -1;
        for (int j = tid; j < cnt; j += 256) {
            float v = cv[j]; int idx = ci[j];
            if (v > bv || (v == bv && idx < bi)) { bv = v; bi = idx; bp = j; }
        }
        sv[tid] = bv; si[tid] = bi; sp[tid] = bp;
        __syncthreads();
        for (int o = 128; o > 0; o >>= 1) {
            if (tid < o) {
                if (sv[tid + o] > sv[tid] || (sv[tid + o] == sv[tid] && si[tid + o] < si[tid])) {
                    sv[tid] = sv[tid + o]; si[tid] = si[tid + o]; sp[tid] = sp[tid + o];
                }
            }
            __syncthreads();
        }
        if (tid == 0) {
            g_topi[n * KTOP + k] = si[0];
            if (sp[0] >= 0) cv[sp[0]] = -CUDART_INF_F;
        }
        __syncthreads();
    }
}

// ---------------- embedding ----------------
__global__ __launch_bounds__(128) void prep_kernel(const float* __restrict__ W) {
    const int np = blockIdx.x;
    const int d = threadIdx.x;
    const int n = np & 3;
    const bool side1 = (np >= 4);
    float S = 0.0f, wx = 0.0f, wy = 0.0f;
    for (int k = 0; k < KTOP; k++) {
        int idx = g_topi[n * KTOP + k];
        int r = side1 ? (idx % HW) : (idx / HW);
        float cx = (float)(r % WDIM) / 60.0f;
        float cy = (float)(r / WDIM) / 60.0f;
        float w0 = W[d * (2 * KTOP) + 2 * k];
        float w1 = W[d * (2 * KTOP) + 2 * k + 1];
        S = fmaf(w0, cx, S);
        S = fmaf(w1, cy, S);
        wx += w0; wy += w1;
    }
    g_E[np * CCH + d] = -S;
    if (np == 0) { g_WX[d] = wx; g_WY[d] = wy; }
}

__global__ __launch_bounds__(256) void final_kernel(const float* __restrict__ x,
                                                    const float* __restrict__ bvec,
                                                    float* __restrict__ out) {
    const int d = blockIdx.x;
    const int np = blockIdx.y;
    const float wx = g_WX[d];
    const float wy = g_WY[d];
    const float e = g_E[np * CCH + d] + bvec[d];
    const size_t base = ((size_t)np * CCH + d) * HW;
    for (int p = threadIdx.x; p < HW; p += 256) {
        float gx = (float)(p % WDIM) / 60.0f;
        float gy = (float)(p / WDIM) / 60.0f;
        out[base + p] = x[base + p] + gx * wx + gy * wy + e;
    }
}

// ---------------- launch ----------------
extern "C" void kernel_launch(void* const* d_in, const int* in_sizes, int n_in,
                              void* d_out, int out_size) {
    (void)in_sizes; (void)n_in; (void)out_size;
    const float* x = (const float*)d_in[0];
    const float* W = (const float*)d_in[1];
    const float* b = (const float*)d_in[2];
    float* out = (float*)d_out;

    gemm_kernel<<<dim3(NBX, NBX, NBATCH), 512>>>(x);
    colfin_kernel<<<dim3(LCPARTS, NBATCH), 256>>>();
    rowfin_kernel<<<dim3(LCPARTS, NBATCH), 256>>>();
    bound_kernel<<<NBATCH, 256>>>();
    collect_kernel<<<dim3(HW, NBATCH), 128>>>();
    select_kernel<<<NBATCH, 256>>>();
    prep_kernel<<<8, 128>>>(W);
    final_kernel<<<dim3(CCH, 8), 256>>>(x, b, out);
}

// round 13
// speedup vs baseline: 4.0714x; 1.0828x over previous
#include <cuda_runtime.h>
#include <cuda_fp16.h>
#include <math_constants.h>
#include <stdint.h>

#define HW    3600
#define WDIM  60
#define CCH   128
#define NBATCH 4
#define KTOP  100
#define CAP   65536
#define NBX   29          // ceil(3600/128)
#define LCPARTS 15
#define SPH   136         // half2 row pitch (conflict-free)

// ---------------- device scratch ----------------
__device__ float g_sm[(size_t)NBATCH * HW * HW];   // 207 MB
__device__ float g_rp[NBATCH * NBX * HW];
__device__ float g_cp[NBATCH * NBX * HW];
__device__ float g_vp[NBATCH * NBX * HW];
__device__ float g_LR[NBATCH * HW];
__device__ float g_LC[NBATCH * HW];
__device__ float g_vmax[NBATCH * HW];
__device__ float g_rowbound[NBATCH * HW];
__device__ float g_lcmin_blk[NBATCH * NBX];
__device__ float g_lcmax_part[NBATCH * LCPARTS];
__device__ float g_thrv[NBATCH];
__device__ int   g_cnt[NBATCH];
__device__ int   g_rowcnt[NBATCH];
__device__ int   g_rowlist[NBATCH * HW];
__device__ float g_cv[NBATCH * CAP];
__device__ int   g_ci[NBATCH * CAP];
__device__ int   g_topi[NBATCH * KTOP];

// ---------------- helpers ----------------
__device__ __forceinline__ void mma_f16(float c[4], const unsigned a[4], const unsigned b[2]) {
    asm volatile(
        "mma.sync.aligned.m16n8k16.row.col.f32.f16.f16.f32 "
        "{%0,%1,%2,%3}, {%4,%5,%6,%7}, {%8,%9}, {%0,%1,%2,%3};"
        : "+f"(c[0]), "+f"(c[1]), "+f"(c[2]), "+f"(c[3])
        : "r"(a[0]), "r"(a[1]), "r"(a[2]), "r"(a[3]), "r"(b[0]), "r"(b[1]));
}
__device__ __forceinline__ unsigned mono_bits(float f) {
    unsigned b = __float_as_uint(f);
    return (b & 0x80000000u) ? ~b : (b | 0x80000000u);
}
__device__ __forceinline__ unsigned h2u(__half2 h) {
    return *reinterpret_cast<unsigned*>(&h);
}

// ---------------- GEMM (fp16 x3 split, m16n8k16, deep-pipelined loader) ----------------
__global__ __launch_bounds__(512, 1) void gemm_kernel(const float* __restrict__ x) {
    __shared__ __align__(16) __half2 Ah[2][8][SPH];
    __shared__ __align__(16) __half2 Al[2][8][SPH];
    __shared__ __align__(16) __half2 Bh[2][8][SPH];
    __shared__ __align__(16) __half2 Bl[2][8][SPH];
    __shared__ float s_rs[4][128];
    __shared__ float s_rm[4][128];
    __shared__ float s_cs[4][128];

    const int n  = blockIdx.z;
    const int l0 = blockIdx.y * 128;
    const int s0 = blockIdx.x * 128;
    const float* A = x + (size_t)n * CCH * HW;
    const float* B = x + (size_t)(n + NBATCH) * CCH * HW;
    const int tid = threadIdx.x;
    const int lane = tid & 31;
    const int wid = tid >> 5;
    const int g = lane >> 2, tig = lane & 3;
    const int wm = wid & 3, wn = wid >> 2;
    const int rb = wm * 32, cb = wn * 32;

    const int side = tid >> 8;
    const int slot = tid & 255;
    const int kp = slot >> 5;
    const int m0 = (slot & 31) << 2;
    const float* P = side ? B : A;
    const int base0 = side ? s0 : l0;
    const bool okc = (base0 + m0) < HW;

    float acc[2][4][4];
#pragma unroll
    for (int mi = 0; mi < 2; mi++)
#pragma unroll
        for (int ni = 0; ni < 4; ni++)
#pragma unroll
            for (int q = 0; q < 4; q++) acc[mi][ni][q] = 0.0f;

    float4 r0, r1;

    auto cvt_sts = [&](int st) {
        __half2 h0 = __floats2half2_rn(r0.x, r1.x);
        __half2 h1 = __floats2half2_rn(r0.y, r1.y);
        __half2 h2 = __floats2half2_rn(r0.z, r1.z);
        __half2 h3 = __floats2half2_rn(r0.w, r1.w);
        float2 b0 = __half22float2(h0), b1 = __half22float2(h1);
        float2 b2 = __half22float2(h2), b3 = __half22float2(h3);
        __half2 l0h = __floats2half2_rn(r0.x - b0.x, r1.x - b0.y);
        __half2 l1h = __floats2half2_rn(r0.y - b1.x, r1.y - b1.y);
        __half2 l2h = __floats2half2_rn(r0.z - b2.x, r1.z - b2.y);
        __half2 l3h = __floats2half2_rn(r0.w - b3.x, r1.w - b3.y);
        __half2* dh = side ? &Bh[st][kp][m0] : &Ah[st][kp][m0];
        __half2* dl = side ? &Bl[st][kp][m0] : &Al[st][kp][m0];
        *reinterpret_cast<uint4*>(dh) = make_uint4(h2u(h0), h2u(h1), h2u(h2), h2u(h3));
        *reinterpret_cast<uint4*>(dl) = make_uint4(h2u(l0h), h2u(l1h), h2u(l2h), h2u(l3h));
    };
    auto ldg_chunk = [&](int c) {
        const int d = c * 16 + kp * 2;
        r0 = okc ? *reinterpret_cast<const float4*>(P + (size_t)d * HW + base0 + m0)
                 : make_float4(0.f, 0.f, 0.f, 0.f);
        r1 = okc ? *reinterpret_cast<const float4*>(P + (size_t)(d + 1) * HW + base0 + m0)
                 : make_float4(0.f, 0.f, 0.f, 0.f);
    };

    ldg_chunk(0);
    cvt_sts(0);
    ldg_chunk(1);
    __syncthreads();

#pragma unroll
    for (int c = 0; c < 8; c++) {
        const int st = c & 1;
        unsigned ah[2][4], al[2][4], bh[4][2], bl[4][2];
#pragma unroll
        for (int mi = 0; mi < 2; mi++) {
            const int mp = rb + mi * 16 + g;
            ah[mi][0] = h2u(Ah[st][tig][mp]);
            ah[mi][1] = h2u(Ah[st][tig][mp + 8]);
            ah[mi][2] = h2u(Ah[st][tig + 4][mp]);
            ah[mi][3] = h2u(Ah[st][tig + 4][mp + 8]);
            al[mi][0] = h2u(Al[st][tig][mp]);
            al[mi][1] = h2u(Al[st][tig][mp + 8]);
            al[mi][2] = h2u(Al[st][tig + 4][mp]);
            al[mi][3] = h2u(Al[st][tig + 4][mp + 8]);
        }
#pragma unroll
        for (int ni = 0; ni < 4; ni++) {
            const int np = cb + ni * 8 + g;
            bh[ni][0] = h2u(Bh[st][tig][np]);
            bh[ni][1] = h2u(Bh[st][tig + 4][np]);
            bl[ni][0] = h2u(Bl[st][tig][np]);
            bl[ni][1] = h2u(Bl[st][tig + 4][np]);
        }
        if (c < 7) cvt_sts(st ^ 1);
        if (c < 6) ldg_chunk(c + 2);

#pragma unroll
        for (int mi = 0; mi < 2; mi++)
#pragma unroll
            for (int ni = 0; ni < 4; ni++)
                mma_f16(acc[mi][ni], ah[mi], bl[ni]);
#pragma unroll
        for (int mi = 0; mi < 2; mi++)
#pragma unroll
            for (int ni = 0; ni < 4; ni++)
                mma_f16(acc[mi][ni], al[mi], bh[ni]);
#pragma unroll
        for (int mi = 0; mi < 2; mi++)
#pragma unroll
            for (int ni = 0; ni < 4; ni++)
                mma_f16(acc[mi][ni], ah[mi], bh[ni]);

        __syncthreads();
    }

    // ---- epilogue: scale, store, exp stats ----
    const float inv = 1.0f / 12.8f;
    float rsum[2][2], rmax[2][2], csum[4][2];
#pragma unroll
    for (int i = 0; i < 2; i++)
#pragma unroll
        for (int r = 0; r < 2; r++) { rsum[i][r] = 0.0f; rmax[i][r] = -CUDART_INF_F; }
#pragma unroll
    for (int i = 0; i < 4; i++) { csum[i][0] = 0.0f; csum[i][1] = 0.0f; }

#pragma unroll
    for (int mi = 0; mi < 2; mi++) {
        const int row0 = l0 + rb + mi * 16 + g;
        const int row1 = row0 + 8;
        const bool rv0 = row0 < HW, rv1 = row1 < HW;
        float* orow0 = g_sm + ((size_t)(n * HW + row0)) * HW;
        float* orow1 = g_sm + ((size_t)(n * HW + row1)) * HW;
#pragma unroll
        for (int ni = 0; ni < 4; ni++) {
            const int sc0 = s0 + cb + ni * 8 + tig * 2;
            const bool cv0 = sc0 < HW, cv1 = (sc0 + 1) < HW;
            float v0 = acc[mi][ni][0] * inv;
            float v1 = acc[mi][ni][1] * inv;
            float v2 = acc[mi][ni][2] * inv;
            float v3 = acc[mi][ni][3] * inv;
            if (rv0 && cv0) *reinterpret_cast<float2*>(orow0 + sc0) = make_float2(v0, v1);
            if (rv1 && cv0) *reinterpret_cast<float2*>(orow1 + sc0) = make_float2(v2, v3);
            float e0 = cv0 ? __expf(v0) : 0.0f;
            float e1 = cv1 ? __expf(v1) : 0.0f;
            float e2 = cv0 ? __expf(v2) : 0.0f;
            float e3 = cv1 ? __expf(v3) : 0.0f;
            rsum[mi][0] += e0 + e1;
            rsum[mi][1] += e2 + e3;
            rmax[mi][0] = fmaxf(rmax[mi][0], fmaxf(cv0 ? v0 : -CUDART_INF_F, cv1 ? v1 : -CUDART_INF_F));
            rmax[mi][1] = fmaxf(rmax[mi][1], fmaxf(cv0 ? v2 : -CUDART_INF_F, cv1 ? v3 : -CUDART_INF_F));
            csum[ni][0] += (rv0 ? e0 : 0.0f) + (rv1 ? e2 : 0.0f);
            csum[ni][1] += (rv0 ? e1 : 0.0f) + (rv1 ? e3 : 0.0f);
        }
    }

#pragma unroll
    for (int m = 1; m < 4; m <<= 1) {
#pragma unroll
        for (int mi = 0; mi < 2; mi++)
#pragma unroll
            for (int r = 0; r < 2; r++) {
                rsum[mi][r] += __shfl_xor_sync(0xffffffffu, rsum[mi][r], m);
                rmax[mi][r] = fmaxf(rmax[mi][r], __shfl_xor_sync(0xffffffffu, rmax[mi][r], m));
            }
    }
    if (tig == 0) {
#pragma unroll
        for (int mi = 0; mi < 2; mi++) {
            const int rr = rb + mi * 16 + g;
            s_rs[wn][rr] = rsum[mi][0];
            s_rs[wn][rr + 8] = rsum[mi][1];
            s_rm[wn][rr] = rmax[mi][0];
            s_rm[wn][rr + 8] = rmax[mi][1];
        }
    }
#pragma unroll
    for (int m = 4; m < 32; m <<= 1) {
#pragma unroll
        for (int ni = 0; ni < 4; ni++)
#pragma unroll
            for (int q = 0; q < 2; q++)
                csum[ni][q] += __shfl_xor_sync(0xffffffffu, csum[ni][q], m);
    }
    if (g == 0) {
#pragma unroll
        for (int ni = 0; ni < 4; ni++) {
            s_cs[wm][cb + ni * 8 + tig * 2]     = csum[ni][0];
            s_cs[wm][cb + ni * 8 + tig * 2 + 1] = csum[ni][1];
        }
    }
    __syncthreads();
    if (tid < 128) {
        float rs = 0.0f, rm = -CUDART_INF_F;
#pragma unroll
        for (int w = 0; w < 4; w++) { rs += s_rs[w][tid]; rm = fmaxf(rm, s_rm[w][tid]); }
        if (l0 + tid < HW) {
            g_rp[(n * NBX + blockIdx.x) * HW + l0 + tid] = rs;
            g_vp[(n * NBX + blockIdx.x) * HW + l0 + tid] = rm;
        }
        float cs = 0.0f;
#pragma unroll
        for (int w = 0; w < 4; w++) cs += s_cs[w][tid];
        if (s0 + tid < HW)
            g_cp[(n * NBX + blockIdx.y) * HW + s0 + tid] = cs;
    }
}

// ---------------- colfin: LC, per-128-block LC min, lcmax partials ----------------
__global__ __launch_bounds__(256) void colfin_kernel() {
    const int n = blockIdx.y;
    const int s = blockIdx.x * 256 + threadIdx.x;
    __shared__ float mn[256], mx[256];
    float v = CUDART_INF_F;
    float hi = -CUDART_INF_F;
    if (s < HW) {
        float acc = 0.0f;
#pragma unroll
        for (int b = 0; b < NBX; b++) acc += g_cp[(n * NBX + b) * HW + s];
        v = logf(acc);
        g_LC[n * HW + s] = v;
        hi = v;
    }
    const int tid = threadIdx.x;
    mn[tid] = v; mx[tid] = hi;
    __syncthreads();
    for (int o = 64; o > 0; o >>= 1) {
        if ((tid & 127) < o) mn[tid] = fminf(mn[tid], mn[tid + o]);
        __syncthreads();
    }
    if ((tid & 127) == 0) {
        int blk = (blockIdx.x * 256 + tid) >> 7;
        if (blk < NBX) g_lcmin_blk[n * NBX + blk] = mn[tid];
    }
    for (int o = 128; o > 0; o >>= 1) {
        if (tid < o) mx[tid] = fmaxf(mx[tid], mx[tid + o]);
        __syncthreads();
    }
    if (tid == 0) g_lcmax_part[n * LCPARTS + blockIdx.x] = mx[0];
}

// ---------------- rowfin: LR, vmax, per-row score upper bound ----------------
__global__ __launch_bounds__(256) void rowfin_kernel() {
    const int n = blockIdx.y;
    const int l = blockIdx.x * 256 + threadIdx.x;
    __shared__ float lcb[NBX];
    if (threadIdx.x < NBX) lcb[threadIdx.x] = g_lcmin_blk[n * NBX + threadIdx.x];
    __syncthreads();
    if (l >= HW) return;
    float s = 0.0f, m = -CUDART_INF_F, rbnd = -CUDART_INF_F;
#pragma unroll
    for (int b = 0; b < NBX; b++) {
        float vp = g_vp[(n * NBX + b) * HW + l];
        s += g_rp[(n * NBX + b) * HW + l];
        m = fmaxf(m, vp);
        rbnd = fmaxf(rbnd, fmaf(2.0f, vp, -lcb[b]));
    }
    float LR = logf(s);
    g_LR[n * HW + l] = LR;
    g_vmax[n * HW + l] = m;
    g_rowbound[n * HW + l] = rbnd - LR;
}

// ---------------- threshold + surviving-row compaction (1024 thr, smem-cached) ----------------
__global__ __launch_bounds__(1024) void bound_kernel() {
    const int n = blockIdx.x;
    const int tid = threadIdx.x;
    __shared__ float Lbuf[HW];
    __shared__ float red1[1024], red2[1024];
    __shared__ int hist[2048];
    __shared__ unsigned ssum[1024];
    __shared__ float s_lmn, s_lmx, s_lcmax, s_t;

    if (tid == 0) {
        float mx = -CUDART_INF_F;
        for (int i = 0; i < LCPARTS; i++) mx = fmaxf(mx, g_lcmax_part[n * LCPARTS + i]);
        s_lcmax = mx;
        g_cnt[n] = 0;
        g_rowcnt[n] = 0;
    }
    __syncthreads();
    const float lcmax = s_lcmax;

    float lmn = CUDART_INF_F, lmx = -CUDART_INF_F;
    for (int l = tid; l < HW; l += 1024) {
        float L = fmaf(2.0f, g_vmax[n * HW + l], -g_LR[n * HW + l]) - lcmax;
        Lbuf[l] = L;
        lmn = fminf(lmn, L); lmx = fmaxf(lmx, L);
    }
    red1[tid] = lmn; red2[tid] = lmx;
    __syncthreads();
    for (int o = 512; o > 0; o >>= 1) {
        if (tid < o) {
            red1[tid] = fminf(red1[tid], red1[tid + o]);
            red2[tid] = fmaxf(red2[tid], red2[tid + o]);
        }
        __syncthreads();
    }
    if (tid == 0) { s_lmn = red1[0]; s_lmx = red2[0]; }
    __syncthreads();
    const float Lmn = s_lmn;
    const float binw = (s_lmx - Lmn) * (1.0f / 2048.0f);

    if (binw < 1e-30f) {
        if (tid == 0) s_t = Lmn;
    } else {
        for (int i = tid; i < 2048; i += 1024) hist[i] = 0;
        __syncthreads();
        for (int l = tid; l < HW; l += 1024) {
            int b = (int)((Lbuf[l] - Lmn) / binw);
            b = max(0, min(2047, b));
            atomicAdd(&hist[b], 1);
        }
        __syncthreads();
        unsigned csum = (unsigned)hist[tid * 2] + (unsigned)hist[tid * 2 + 1];
        ssum[tid] = csum;
        __syncthreads();
        for (int off = 1; off < 1024; off <<= 1) {
            unsigned v = (tid + off < 1024) ? ssum[tid + off] : 0u;
            __syncthreads();
            ssum[tid] += v;
            __syncthreads();
        }
        unsigned mine = ssum[tid];
        unsigned nxt = (tid < 1023) ? ssum[tid + 1] : 0u;
        if (mine >= KTOP && nxt < KTOP) {
            unsigned cum = nxt;
            int b = tid * 2 + 1;
            for (; b > tid * 2; b--) {
                cum += (unsigned)hist[b];
                if (cum >= KTOP) break;
            }
            s_t = Lmn + (float)(b - 1) * binw;   // one-bin safety margin
        }
    }
    __syncthreads();
    const float t = s_t;
    if (tid == 0) g_thrv[n] = t;
    // compact surviving rows
    for (int l = tid; l < HW; l += 1024) {
        if (g_rowbound[n * HW + l] >= t) {
            int p = atomicAdd(&g_rowcnt[n], 1);
            g_rowlist[n * HW + p] = l;
        }
    }
}

// ---------------- collect: block-pruned scan over surviving rows ----------------
__global__ __launch_bounds__(128) void collect_kernel() {
    const int n = blockIdx.y;
    const float t = g_thrv[n];
    const int rcnt = g_rowcnt[n];
    const int tid = threadIdx.x;
    __shared__ unsigned s_mask;
    const float* LC = g_LC + n * HW;

    for (int ri = blockIdx.x; ri < rcnt; ri += gridDim.x) {
        const int l = g_rowlist[n * HW + ri];
        const float LR = g_LR[n * HW + l];
        if (tid < 32) {
            bool flag = false;
            if (tid < NBX) {
                float vp = g_vp[(n * NBX + tid) * HW + l];
                flag = (fmaf(2.0f, vp, -LR) - g_lcmin_blk[n * NBX + tid]) >= t;
            }
            unsigned m = __ballot_sync(0xffffffffu, flag);
            if (tid == 0) s_mask = m;
        }
        __syncthreads();
        unsigned mask = s_mask;
        const float* row = g_sm + ((size_t)(n * HW + l)) * HW;
        while (mask) {
            int b = __ffs(mask) - 1;
            mask &= mask - 1;
            int s = b * 128 + tid;
            if (s < HW) {
                float sc = fmaf(2.0f, row[s], -LR) - LC[s];
                if (sc >= t) {
                    int p = atomicAdd(&g_cnt[n], 1);
                    if (p < CAP) {
                        g_cv[n * CAP + p] = sc;
                        g_ci[n * CAP + p] = l * HW + s;
                    }
                }
            }
        }
        __syncthreads();
    }
}

// ---------------- top-100: smem bitonic sort on packed keys ----------------
__global__ __launch_bounds__(256) void select_kernel() {
    const int n = blockIdx.x;
    const int tid = threadIdx.x;
    int cnt = g_cnt[n];
    if (cnt > CAP) cnt = CAP;
    float* cv = g_cv + n * CAP;
    int* ci = g_ci + n * CAP;

    if (cnt <= 2048) {
        __shared__ unsigned long long key[2048];
        for (int i = tid; i < 2048; i += 256) {
            unsigned long long k = 0ull;
            if (i < cnt)
                k = ((unsigned long long)mono_bits(cv[i]) << 32) |
                    (unsigned long long)(0xFFFFFFFFu - (unsigned)ci[i]);
            key[i] = k;
        }
        __syncthreads();
        for (int kk = 2; kk <= 2048; kk <<= 1) {
            for (int j = kk >> 1; j > 0; j >>= 1) {
                for (int i = tid; i < 2048; i += 256) {
                    int ixj = i ^ j;
                    if (ixj > i) {
                        bool dirDesc = ((i & kk) == 0);
                        unsigned long long a = key[i], b = key[ixj];
                        if ((a < b) == dirDesc) { key[i] = b; key[ixj] = a; }
                    }
                }
                __syncthreads();
            }
        }
        if (tid < KTOP)
            g_topi[n * KTOP + tid] = (int)(0xFFFFFFFFu - (unsigned)(key[tid] & 0xFFFFFFFFull));
        return;
    }

    // fallback: iterative argmax
    __shared__ float sv[256];
    __shared__ int si[256];
    __shared__ int sp[256];
    for (int k = 0; k < KTOP; k++) {
        float bv = -CUDART_INF_F; int bi = 0x7FFFFFFF; int bp = -1;
        for (int j = tid; j < cnt; j += 256) {
            float v = cv[j]; int idx = ci[j];
            if (v > bv || (v == bv && idx < bi)) { bv = v; bi = idx; bp = j; }
        }
        sv[tid] = bv; si[tid] = bi; sp[tid] = bp;
        __syncthreads();
        for (int o = 128; o > 0; o >>= 1) {
            if (tid < o) {
                if (sv[tid + o] > sv[tid] || (sv[tid + o] == sv[tid] && si[tid + o] < si[tid])) {
                    sv[tid] = sv[tid + o]; si[tid] = si[tid + o]; sp[tid] = sp[tid + o];
                }
            }
            __syncthreads();
        }
        if (tid == 0) {
            g_topi[n * KTOP + k] = si[0];
            if (sp[0] >= 0) cv[sp[0]] = -CUDART_INF_F;
        }
        __syncthreads();
    }
}

// ---------------- final (prep fused): out = x + gx*wx + gy*wy + e ----------------
__global__ __launch_bounds__(256) void final_kernel(const float* __restrict__ x,
                                                    const float* __restrict__ W,
                                                    const float* __restrict__ bvec,
                                                    float* __restrict__ out) {
    const int d = blockIdx.x;
    const int np = blockIdx.y;
    const int n = np & 3;
    const bool side1 = (np >= 4);
    const int tid = threadIdx.x;

    __shared__ float rS[128], rX[128], rY[128];
    __shared__ float s_e, s_wx, s_wy;
    if (tid < 128) {
        float pS = 0.0f, px = 0.0f, py = 0.0f;
        if (tid < KTOP) {
            int idx = g_topi[n * KTOP + tid];
            int r = side1 ? (idx % HW) : (idx / HW);
            float cx = (float)(r % WDIM) / 60.0f;
            float cy = (float)(r / WDIM) / 60.0f;
            float w0 = W[d * (2 * KTOP) + 2 * tid];
            float w1 = W[d * (2 * KTOP) + 2 * tid + 1];
            pS = fmaf(w0, cx, w1 * cy);
            px = w0; py = w1;
        }
        rS[tid] = pS; rX[tid] = px; rY[tid] = py;
    }
    __syncthreads();
    for (int o = 64; o > 0; o >>= 1) {
        if (tid < o) {
            rS[tid] += rS[tid + o];
            rX[tid] += rX[tid + o];
            rY[tid] += rY[tid + o];
        }
        __syncthreads();
    }
    if (tid == 0) {
        s_e = -rS[0] + bvec[d];
        s_wx = rX[0];
        s_wy = rY[0];
    }
    __syncthreads();
    const float wx = s_wx, wy = s_wy, e = s_e;
    const size_t base = ((size_t)np * CCH + d) * HW;
    for (int p = tid; p < HW; p += 256) {
        float gx = (float)(p % WDIM) / 60.0f;
        float gy = (float)(p / WDIM) / 60.0f;
        out[base + p] = x[base + p] + gx * wx + gy * wy + e;
    }
}

// ---------------- launch ----------------
extern "C" void kernel_launch(void* const* d_in, const int* in_sizes, int n_in,
                              void* d_out, int out_size) {
    (void)in_sizes; (void)n_in; (void)out_size;
    const float* x = (const float*)d_in[0];
    const float* W = (const float*)d_in[1];
    const float* b = (const float*)d_in[2];
    float* out = (float*)d_out;

    gemm_kernel<<<dim3(NBX, NBX, NBATCH), 512>>>(x);
    colfin_kernel<<<dim3(LCPARTS, NBATCH), 256>>>();
    rowfin_kernel<<<dim3(LCPARTS, NBATCH), 256>>>();
    bound_kernel<<<NBATCH, 1024>>>();
    collect_kernel<<<dim3(64, NBATCH), 128>>>();
    select_kernel<<<NBATCH, 256>>>();
    final_kernel<<<dim3(CCH, 8), 256>>>(x, W, b, out);
}

// round 14
// speedup vs baseline: 4.2125x; 1.0346x over previous
#include <cuda_runtime.h>
#include <cuda_fp16.h>
#include <math_constants.h>
#include <stdint.h>

#define HW    3600
#define WDIM  60
#define CCH   128
#define NBATCH 4
#define KTOP  100
#define CAP   65536
#define NBY   29          // row blocks (128)
#define NBXS  57          // col blocks (64)
#define NBX   29          // 128-col blocks (pruning)
#define LCPARTS 15
#define SPH   136         // A half2 row pitch
#define SPHB  72          // B half2 row pitch

// ---------------- device scratch ----------------
__device__ float g_sm[(size_t)NBATCH * HW * HW];   // 207 MB
__device__ float g_rp[NBATCH * NBXS * HW];
__device__ float g_cp[NBATCH * NBY * HW];
__device__ float g_vp[NBATCH * NBXS * HW];
__device__ float g_LR[NBATCH * HW];
__device__ float g_LC[NBATCH * HW];
__device__ float g_vmax[NBATCH * HW];
__device__ float g_rowbound[NBATCH * HW];
__device__ float g_lcmin_blk[NBATCH * NBX];
__device__ float g_lcmax_part[NBATCH * LCPARTS];
__device__ float g_thrv[NBATCH];
__device__ int   g_cnt[NBATCH];
__device__ int   g_rowcnt[NBATCH];
__device__ int   g_rowlist[NBATCH * HW];
__device__ float g_cv[NBATCH * CAP];
__device__ int   g_ci[NBATCH * CAP];
__device__ int   g_topi[NBATCH * KTOP];

// ---------------- helpers ----------------
__device__ __forceinline__ void mma_f16(float c[4], const unsigned a[4], const unsigned b[2]) {
    asm volatile(
        "mma.sync.aligned.m16n8k16.row.col.f32.f16.f16.f32 "
        "{%0,%1,%2,%3}, {%4,%5,%6,%7}, {%8,%9}, {%0,%1,%2,%3};"
        : "+f"(c[0]), "+f"(c[1]), "+f"(c[2]), "+f"(c[3])
        : "r"(a[0]), "r"(a[1]), "r"(a[2]), "r"(a[3]), "r"(b[0]), "r"(b[1]));
}
__device__ __forceinline__ unsigned mono_bits(float f) {
    unsigned b = __float_as_uint(f);
    return (b & 0x80000000u) ? ~b : (b | 0x80000000u);
}
__device__ __forceinline__ unsigned h2u(__half2 h) {
    return *reinterpret_cast<unsigned*>(&h);
}

// ---------------- GEMM: fp16 x3 split, 128x64 tile, 256 thr, 2 CTA/SM ----------------
__global__ __launch_bounds__(256, 2) void gemm_kernel(const float* __restrict__ x) {
    __shared__ __align__(16) __half2 Ah[2][8][SPH];
    __shared__ __align__(16) __half2 Al[2][8][SPH];
    __shared__ __align__(16) __half2 Bh[2][8][SPHB];
    __shared__ __align__(16) __half2 Bl[2][8][SPHB];
    __shared__ float s_rs[2][128];
    __shared__ float s_rm[2][128];
    __shared__ float s_cs[4][64];

    const int n  = blockIdx.z;
    const int l0 = blockIdx.y * 128;
    const int s0 = blockIdx.x * 64;
    const float* A = x + (size_t)n * CCH * HW;
    const float* B = x + (size_t)(n + NBATCH) * CCH * HW;
    const int tid = threadIdx.x;
    const int lane = tid & 31;
    const int wid = tid >> 5;
    const int g = lane >> 2, tig = lane & 3;
    const int wm = wid & 3, wn = wid >> 2;
    const int rb = wm * 32, cb = wn * 32;

    // loader: all 256 threads -> A; first 128 threads also -> B
    const int kpA = tid >> 5;               // 0..7
    const int m0A = (lane) << 2;            // 0..124
    const bool okA = (l0 + m0A) < HW;
    const int kpB = (tid & 127) >> 4;       // 0..7
    const int m0B = (tid & 15) << 2;        // 0..60
    const bool doB = tid < 128;
    const bool okB = (s0 + m0B) < HW;

    float acc[2][4][4];
#pragma unroll
    for (int mi = 0; mi < 2; mi++)
#pragma unroll
        for (int ni = 0; ni < 4; ni++)
#pragma unroll
            for (int q = 0; q < 4; q++) acc[mi][ni][q] = 0.0f;

    float4 rA0, rA1, rB0, rB1;

    auto ldg_chunk = [&](int c) {
        const int dA = c * 16 + kpA * 2;
        rA0 = okA ? *reinterpret_cast<const float4*>(A + (size_t)dA * HW + l0 + m0A)
                  : make_float4(0.f, 0.f, 0.f, 0.f);
        rA1 = okA ? *reinterpret_cast<const float4*>(A + (size_t)(dA + 1) * HW + l0 + m0A)
                  : make_float4(0.f, 0.f, 0.f, 0.f);
        if (doB) {
            const int dB = c * 16 + kpB * 2;
            rB0 = okB ? *reinterpret_cast<const float4*>(B + (size_t)dB * HW + s0 + m0B)
                      : make_float4(0.f, 0.f, 0.f, 0.f);
            rB1 = okB ? *reinterpret_cast<const float4*>(B + (size_t)(dB + 1) * HW + s0 + m0B)
                      : make_float4(0.f, 0.f, 0.f, 0.f);
        }
    };
    auto cvt_sts = [&](int st) {
        {
            __half2 h0 = __floats2half2_rn(rA0.x, rA1.x);
            __half2 h1 = __floats2half2_rn(rA0.y, rA1.y);
            __half2 h2 = __floats2half2_rn(rA0.z, rA1.z);
            __half2 h3 = __floats2half2_rn(rA0.w, rA1.w);
            float2 b0 = __half22float2(h0), b1 = __half22float2(h1);
            float2 b2 = __half22float2(h2), b3 = __half22float2(h3);
            __half2 L0 = __floats2half2_rn(rA0.x - b0.x, rA1.x - b0.y);
            __half2 L1 = __floats2half2_rn(rA0.y - b1.x, rA1.y - b1.y);
            __half2 L2 = __floats2half2_rn(rA0.z - b2.x, rA1.z - b2.y);
            __half2 L3 = __floats2half2_rn(rA0.w - b3.x, rA1.w - b3.y);
            *reinterpret_cast<uint4*>(&Ah[st][kpA][m0A]) = make_uint4(h2u(h0), h2u(h1), h2u(h2), h2u(h3));
            *reinterpret_cast<uint4*>(&Al[st][kpA][m0A]) = make_uint4(h2u(L0), h2u(L1), h2u(L2), h2u(L3));
        }
        if (doB) {
            __half2 h0 = __floats2half2_rn(rB0.x, rB1.x);
            __half2 h1 = __floats2half2_rn(rB0.y, rB1.y);
            __half2 h2 = __floats2half2_rn(rB0.z, rB1.z);
            __half2 h3 = __floats2half2_rn(rB0.w, rB1.w);
            float2 b0 = __half22float2(h0), b1 = __half22float2(h1);
            float2 b2 = __half22float2(h2), b3 = __half22float2(h3);
            __half2 L0 = __floats2half2_rn(rB0.x - b0.x, rB1.x - b0.y);
            __half2 L1 = __floats2half2_rn(rB0.y - b1.x, rB1.y - b1.y);
            __half2 L2 = __floats2half2_rn(rB0.z - b2.x, rB1.z - b2.y);
            __half2 L3 = __floats2half2_rn(rB0.w - b3.x, rB1.w - b3.y);
            *reinterpret_cast<uint4*>(&Bh[st][kpB][m0B]) = make_uint4(h2u(h0), h2u(h1), h2u(h2), h2u(h3));
            *reinterpret_cast<uint4*>(&Bl[st][kpB][m0B]) = make_uint4(h2u(L0), h2u(L1), h2u(L2), h2u(L3));
        }
    };

    ldg_chunk(0);
    cvt_sts(0);
    ldg_chunk(1);
    __syncthreads();

#pragma unroll
    for (int c = 0; c < 8; c++) {
        const int st = c & 1;
        unsigned ah[2][4], al[2][4], bh[4][2], bl[4][2];
#pragma unroll
        for (int mi = 0; mi < 2; mi++) {
            const int mp = rb + mi * 16 + g;
            ah[mi][0] = h2u(Ah[st][tig][mp]);
            ah[mi][1] = h2u(Ah[st][tig][mp + 8]);
            ah[mi][2] = h2u(Ah[st][tig + 4][mp]);
            ah[mi][3] = h2u(Ah[st][tig + 4][mp + 8]);
            al[mi][0] = h2u(Al[st][tig][mp]);
            al[mi][1] = h2u(Al[st][tig][mp + 8]);
            al[mi][2] = h2u(Al[st][tig + 4][mp]);
            al[mi][3] = h2u(Al[st][tig + 4][mp + 8]);
        }
#pragma unroll
        for (int ni = 0; ni < 4; ni++) {
            const int np = cb + ni * 8 + g;
            bh[ni][0] = h2u(Bh[st][tig][np]);
            bh[ni][1] = h2u(Bh[st][tig + 4][np]);
            bl[ni][0] = h2u(Bl[st][tig][np]);
            bl[ni][1] = h2u(Bl[st][tig + 4][np]);
        }
        if (c < 7) cvt_sts(st ^ 1);
        if (c < 6) ldg_chunk(c + 2);

#pragma unroll
        for (int mi = 0; mi < 2; mi++)
#pragma unroll
            for (int ni = 0; ni < 4; ni++)
                mma_f16(acc[mi][ni], ah[mi], bl[ni]);
#pragma unroll
        for (int mi = 0; mi < 2; mi++)
#pragma unroll
            for (int ni = 0; ni < 4; ni++)
                mma_f16(acc[mi][ni], al[mi], bh[ni]);
#pragma unroll
        for (int mi = 0; mi < 2; mi++)
#pragma unroll
            for (int ni = 0; ni < 4; ni++)
                mma_f16(acc[mi][ni], ah[mi], bh[ni]);

        __syncthreads();
    }

    // ---- epilogue: scale, store, exp stats ----
    const float inv = 1.0f / 12.8f;
    float rsum[2][2], rmax[2][2], csum[4][2];
#pragma unroll
    for (int i = 0; i < 2; i++)
#pragma unroll
        for (int r = 0; r < 2; r++) { rsum[i][r] = 0.0f; rmax[i][r] = -CUDART_INF_F; }
#pragma unroll
    for (int i = 0; i < 4; i++) { csum[i][0] = 0.0f; csum[i][1] = 0.0f; }

#pragma unroll
    for (int mi = 0; mi < 2; mi++) {
        const int row0 = l0 + rb + mi * 16 + g;
        const int row1 = row0 + 8;
        const bool rv0 = row0 < HW, rv1 = row1 < HW;
        float* orow0 = g_sm + ((size_t)(n * HW + row0)) * HW;
        float* orow1 = g_sm + ((size_t)(n * HW + row1)) * HW;
#pragma unroll
        for (int ni = 0; ni < 4; ni++) {
            const int sc0 = s0 + cb + ni * 8 + tig * 2;
            const bool cv0 = sc0 < HW, cv1 = (sc0 + 1) < HW;
            float v0 = acc[mi][ni][0] * inv;
            float v1 = acc[mi][ni][1] * inv;
            float v2 = acc[mi][ni][2] * inv;
            float v3 = acc[mi][ni][3] * inv;
            if (rv0 && cv0) *reinterpret_cast<float2*>(orow0 + sc0) = make_float2(v0, v1);
            if (rv1 && cv0) *reinterpret_cast<float2*>(orow1 + sc0) = make_float2(v2, v3);
            float e0 = cv0 ? __expf(v0) : 0.0f;
            float e1 = cv1 ? __expf(v1) : 0.0f;
            float e2 = cv0 ? __expf(v2) : 0.0f;
            float e3 = cv1 ? __expf(v3) : 0.0f;
            rsum[mi][0] += e0 + e1;
            rsum[mi][1] += e2 + e3;
            rmax[mi][0] = fmaxf(rmax[mi][0], fmaxf(cv0 ? v0 : -CUDART_INF_F, cv1 ? v1 : -CUDART_INF_F));
            rmax[mi][1] = fmaxf(rmax[mi][1], fmaxf(cv0 ? v2 : -CUDART_INF_F, cv1 ? v3 : -CUDART_INF_F));
            csum[ni][0] += (rv0 ? e0 : 0.0f) + (rv1 ? e2 : 0.0f);
            csum[ni][1] += (rv0 ? e1 : 0.0f) + (rv1 ? e3 : 0.0f);
        }
    }

#pragma unroll
    for (int m = 1; m < 4; m <<= 1) {
#pragma unroll
        for (int mi = 0; mi < 2; mi++)
#pragma unroll
            for (int r = 0; r < 2; r++) {
                rsum[mi][r] += __shfl_xor_sync(0xffffffffu, rsum[mi][r], m);
                rmax[mi][r] = fmaxf(rmax[mi][r], __shfl_xor_sync(0xffffffffu, rmax[mi][r], m));
            }
    }
    if (tig == 0) {
#pragma unroll
        for (int mi = 0; mi < 2; mi++) {
            const int rr = rb + mi * 16 + g;
            s_rs[wn][rr] = rsum[mi][0];
            s_rs[wn][rr + 8] = rsum[mi][1];
            s_rm[wn][rr] = rmax[mi][0];
            s_rm[wn][rr + 8] = rmax[mi][1];
        }
    }
#pragma unroll
    for (int m = 4; m < 32; m <<= 1) {
#pragma unroll
        for (int ni = 0; ni < 4; ni++)
#pragma unroll
            for (int q = 0; q < 2; q++)
                csum[ni][q] += __shfl_xor_sync(0xffffffffu, csum[ni][q], m);
    }
    if (g == 0) {
#pragma unroll
        for (int ni = 0; ni < 4; ni++) {
            s_cs[wm][cb + ni * 8 + tig * 2]     = csum[ni][0];
            s_cs[wm][cb + ni * 8 + tig * 2 + 1] = csum[ni][1];
        }
    }
    __syncthreads();
    if (tid < 128 && l0 + tid < HW) {
        float rs = s_rs[0][tid] + s_rs[1][tid];
        float rm = fmaxf(s_rm[0][tid], s_rm[1][tid]);
        g_rp[(n * NBXS + blockIdx.x) * HW + l0 + tid] = rs;
        g_vp[(n * NBXS + blockIdx.x) * HW + l0 + tid] = rm;
    }
    if (tid < 64 && s0 + tid < HW) {
        float cs = s_cs[0][tid] + s_cs[1][tid] + s_cs[2][tid] + s_cs[3][tid];
        g_cp[(n * NBY + blockIdx.y) * HW + s0 + tid] = cs;
    }
}

// ---------------- colfin: LC, per-128-block LC min, lcmax partials ----------------
__global__ __launch_bounds__(256) void colfin_kernel() {
    const int n = blockIdx.y;
    const int s = blockIdx.x * 256 + threadIdx.x;
    __shared__ float mn[256], mx[256];
    float v = CUDART_INF_F;
    float hi = -CUDART_INF_F;
    if (s < HW) {
        float acc = 0.0f;
#pragma unroll
        for (int b = 0; b < NBY; b++) acc += g_cp[(n * NBY + b) * HW + s];
        v = logf(acc);
        g_LC[n * HW + s] = v;
        hi = v;
    }
    const int tid = threadIdx.x;
    mn[tid] = v; mx[tid] = hi;
    __syncthreads();
    for (int o = 64; o > 0; o >>= 1) {
        if ((tid & 127) < o) mn[tid] = fminf(mn[tid], mn[tid + o]);
        __syncthreads();
    }
    if ((tid & 127) == 0) {
        int blk = (blockIdx.x * 256 + tid) >> 7;
        if (blk < NBX) g_lcmin_blk[n * NBX + blk] = mn[tid];
    }
    for (int o = 128; o > 0; o >>= 1) {
        if (tid < o) mx[tid] = fmaxf(mx[tid], mx[tid + o]);
        __syncthreads();
    }
    if (tid == 0) g_lcmax_part[n * LCPARTS + blockIdx.x] = mx[0];
}

// ---------------- rowfin: LR, vmax, per-row score upper bound ----------------
__global__ __launch_bounds__(256) void rowfin_kernel() {
    const int n = blockIdx.y;
    const int l = blockIdx.x * 256 + threadIdx.x;
    __shared__ float lcb[NBX];
    if (threadIdx.x < NBX) lcb[threadIdx.x] = g_lcmin_blk[n * NBX + threadIdx.x];
    __syncthreads();
    if (l >= HW) return;
    float s = 0.0f, m = -CUDART_INF_F, rbnd = -CUDART_INF_F;
#pragma unroll
    for (int b = 0; b < NBXS; b++) {
        float vp = g_vp[(n * NBXS + b) * HW + l];
        s += g_rp[(n * NBXS + b) * HW + l];
        m = fmaxf(m, vp);
        rbnd = fmaxf(rbnd, fmaf(2.0f, vp, -lcb[b >> 1]));
    }
    float LR = logf(s);
    g_LR[n * HW + l] = LR;
    g_vmax[n * HW + l] = m;
    g_rowbound[n * HW + l] = rbnd - LR;
}

// ---------------- threshold + surviving-row compaction ----------------
__global__ __launch_bounds__(1024) void bound_kernel() {
    const int n = blockIdx.x;
    const int tid = threadIdx.x;
    __shared__ float Lbuf[HW];
    __shared__ float red1[1024], red2[1024];
    __shared__ int hist[2048];
    __shared__ unsigned ssum[1024];
    __shared__ float s_lmn, s_lmx, s_lcmax, s_t;

    if (tid == 0) {
        float mx = -CUDART_INF_F;
        for (int i = 0; i < LCPARTS; i++) mx = fmaxf(mx, g_lcmax_part[n * LCPARTS + i]);
        s_lcmax = mx;
        g_cnt[n] = 0;
        g_rowcnt[n] = 0;
    }
    __syncthreads();
    const float lcmax = s_lcmax;

    float lmn = CUDART_INF_F, lmx = -CUDART_INF_F;
    for (int l = tid; l < HW; l += 1024) {
        float L = fmaf(2.0f, g_vmax[n * HW + l], -g_LR[n * HW + l]) - lcmax;
        Lbuf[l] = L;
        lmn = fminf(lmn, L); lmx = fmaxf(lmx, L);
    }
    red1[tid] = lmn; red2[tid] = lmx;
    __syncthreads();
    for (int o = 512; o > 0; o >>= 1) {
        if (tid < o) {
            red1[tid] = fminf(red1[tid], red1[tid + o]);
            red2[tid] = fmaxf(red2[tid], red2[tid + o]);
        }
        __syncthreads();
    }
    if (tid == 0) { s_lmn = red1[0]; s_lmx = red2[0]; }
    __syncthreads();
    const float Lmn = s_lmn;
    const float binw = (s_lmx - Lmn) * (1.0f / 2048.0f);

    if (binw < 1e-30f) {
        if (tid == 0) s_t = Lmn;
    } else {
        for (int i = tid; i < 2048; i += 1024) hist[i] = 0;
        __syncthreads();
        for (int l = tid; l < HW; l += 1024) {
            int b = (int)((Lbuf[l] - Lmn) / binw);
            b = max(0, min(2047, b));
            atomicAdd(&hist[b], 1);
        }
        __syncthreads();
        unsigned csum = (unsigned)hist[tid * 2] + (unsigned)hist[tid * 2 + 1];
        ssum[tid] = csum;
        __syncthreads();
        for (int off = 1; off < 1024; off <<= 1) {
            unsigned v = (tid + off < 1024) ? ssum[tid + off] : 0u;
            __syncthreads();
            ssum[tid] += v;
            __syncthreads();
        }
        unsigned mine = ssum[tid];
        unsigned nxt = (tid < 1023) ? ssum[tid + 1] : 0u;
        if (mine >= KTOP && nxt < KTOP) {
            unsigned cum = nxt;
            int b = tid * 2 + 1;
            for (; b > tid * 2; b--) {
                cum += (unsigned)hist[b];
                if (cum >= KTOP) break;
            }
            s_t = Lmn + (float)(b - 1) * binw;   // one-bin safety margin
        }
    }
    __syncthreads();
    const float t = s_t;
    if (tid == 0) g_thrv[n] = t;
    for (int l = tid; l < HW; l += 1024) {
        if (g_rowbound[n * HW + l] >= t) {
            int p = atomicAdd(&g_rowcnt[n], 1);
            g_rowlist[n * HW + p] = l;
        }
    }
}

// ---------------- collect: block-pruned scan over surviving rows ----------------
__global__ __launch_bounds__(128) void collect_kernel() {
    const int n = blockIdx.y;
    const float t = g_thrv[n];
    const int rcnt = g_rowcnt[n];
    const int tid = threadIdx.x;
    __shared__ unsigned s_mask;
    const float* LC = g_LC + n * HW;

    for (int ri = blockIdx.x; ri < rcnt; ri += gridDim.x) {
        const int l = g_rowlist[n * HW + ri];
        const float LR = g_LR[n * HW + l];
        if (tid < 32) {
            bool flag = false;
            if (tid < NBX) {
                float vp = g_vp[(n * NBXS + 2 * tid) * HW + l];
                if (2 * tid + 1 < NBXS)
                    vp = fmaxf(vp, g_vp[(n * NBXS + 2 * tid + 1) * HW + l]);
                flag = (fmaf(2.0f, vp, -LR) - g_lcmin_blk[n * NBX + tid]) >= t;
            }
            unsigned m = __ballot_sync(0xffffffffu, flag);
            if (tid == 0) s_mask = m;
        }
        __syncthreads();
        unsigned mask = s_mask;
        const float* row = g_sm + ((size_t)(n * HW + l)) * HW;
        while (mask) {
            int b = __ffs(mask) - 1;
            mask &= mask - 1;
            int s = b * 128 + tid;
            if (s < HW) {
                float sc = fmaf(2.0f, row[s], -LR) - LC[s];
                if (sc >= t) {
                    int p = atomicAdd(&g_cnt[n], 1);
                    if (p < CAP) {
                        g_cv[n * CAP + p] = sc;
                        g_ci[n * CAP + p] = l * HW + s;
                    }
                }
            }
        }
        __syncthreads();
    }
}

// ---------------- top-100: smem bitonic sort on packed keys ----------------
__global__ __launch_bounds__(256) void select_kernel() {
    const int n = blockIdx.x;
    const int tid = threadIdx.x;
    int cnt = g_cnt[n];
    if (cnt > CAP) cnt = CAP;
    float* cv = g_cv + n * CAP;
    int* ci = g_ci + n * CAP;

    if (cnt <= 2048) {
        __shared__ unsigned long long key[2048];
        for (int i = tid; i < 2048; i += 256) {
            unsigned long long k = 0ull;
            if (i < cnt)
                k = ((unsigned long long)mono_bits(cv[i]) << 32) |
                    (unsigned long long)(0xFFFFFFFFu - (unsigned)ci[i]);
            key[i] = k;
        }
        __syncthreads();
        for (int kk = 2; kk <= 2048; kk <<= 1) {
            for (int j = kk >> 1; j > 0; j >>= 1) {
                for (int i = tid; i < 2048; i += 256) {
                    int ixj = i ^ j;
                    if (ixj > i) {
                        bool dirDesc = ((i & kk) == 0);
                        unsigned long long a = key[i], b = key[ixj];
                        if ((a < b) == dirDesc) { key[i] = b; key[ixj] = a; }
                    }
                }
                __syncthreads();
            }
        }
        if (tid < KTOP)
            g_topi[n * KTOP + tid] = (int)(0xFFFFFFFFu - (unsigned)(key[tid] & 0xFFFFFFFFull));
        return;
    }

    __shared__ float sv[256];
    __shared__ int si[256];
    __shared__ int sp[256];
    for (int k = 0; k < KTOP; k++) {
        float bv = -CUDART_INF_F; int bi = 0x7FFFFFFF; int bp = -1;
        for (int j = tid; j < cnt; j += 256) {
            float v = cv[j]; int idx = ci[j];
            if (v > bv || (v == bv && idx < bi)) { bv = v; bi = idx; bp = j; }
        }
        sv[tid] = bv; si[tid] = bi; sp[tid] = bp;
        __syncthreads();
        for (int o = 128; o > 0; o >>= 1) {
            if (tid < o) {
                if (sv[tid + o] > sv[tid] || (sv[tid + o] == sv[tid] && si[tid + o] < si[tid])) {
                    sv[tid] = sv[tid + o]; si[tid] = si[tid + o]; sp[tid] = sp[tid + o];
                }
            }
            __syncthreads();
        }
        if (tid == 0) {
            g_topi[n * KTOP + k] = si[0];
            if (sp[0] >= 0) cv[sp[0]] = -CUDART_INF_F;
        }
        __syncthreads();
    }
}

// ---------------- final (prep fused) ----------------
__global__ __launch_bounds__(256) void final_kernel(const float* __restrict__ x,
                                                    const float* __restrict__ W,
                                                    const float* __restrict__ bvec,
                                                    float* __restrict__ out) {
    const int d = blockIdx.x;
    const int np = blockIdx.y;
    const int n = np & 3;
    const bool side1 = (np >= 4);
    const int tid = threadIdx.x;

    __shared__ float rS[128], rX[128], rY[128];
    __shared__ float s_e, s_wx, s_wy;
    if (tid < 128) {
        float pS = 0.0f, px = 0.0f, py = 0.0f;
        if (tid < KTOP) {
            int idx = g_topi[n * KTOP + tid];
            int r = side1 ? (idx % HW) : (idx / HW);
            float cx = (float)(r % WDIM) / 60.0f;
            float cy = (float)(r / WDIM) / 60.0f;
            float w0 = W[d * (2 * KTOP) + 2 * tid];
            float w1 = W[d * (2 * KTOP) + 2 * tid + 1];
            pS = fmaf(w0, cx, w1 * cy);
            px = w0; py = w1;
        }
        rS[tid] = pS; rX[tid] = px; rY[tid] = py;
    }
    __syncthreads();
    for (int o = 64; o > 0; o >>= 1) {
        if (tid < o) {
            rS[tid] += rS[tid + o];
            rX[tid] += rX[tid + o];
            rY[tid] += rY[tid + o];
        }
        __syncthreads();
    }
    if (tid == 0) {
        s_e = -rS[0] + bvec[d];
        s_wx = rX[0];
        s_wy = rY[0];
    }
    __syncthreads();
    const float wx = s_wx, wy = s_wy, e = s_e;
    const size_t base = ((size_t)np * CCH + d) * HW;
    for (int p = tid; p < HW; p += 256) {
        float gx = (float)(p % WDIM) / 60.0f;
        float gy = (float)(p / WDIM) / 60.0f;
        out[base + p] = x[base + p] + gx * wx + gy * wy + e;
    }
}

// ---------------- launch ----------------
extern "C" void kernel_launch(void* const* d_in, const int* in_sizes, int n_in,
                              void* d_out, int out_size) {
    (void)in_sizes; (void)n_in; (void)out_size;
    const float* x = (const float*)d_in[0];
    const float* W = (const float*)d_in[1];
    const float* b = (const float*)d_in[2];
    float* out = (float*)d_out;

    gemm_kernel<<<dim3(NBXS, NBY, NBATCH), 256>>>(x);
    colfin_kernel<<<dim3(LCPARTS, NBATCH), 256>>>();
    rowfin_kernel<<<dim3(LCPARTS, NBATCH), 256>>>();
    bound_kernel<<<NBATCH, 1024>>>();
    collect_kernel<<<dim3(64, NBATCH), 128>>>();
    select_kernel<<<NBATCH, 256>>>();
    final_kernel<<<dim3(CCH, 8), 256>>>(x, W, b, out);
}